// round 2
// baseline (speedup 1.0000x reference)
#include <cuda_runtime.h>
#include <string.h>

// ---------------- problem constants (fixed by dataset) ----------------
#define KB    2        // batch
#define KNV   6        // views
#define KM    1369     // tokens (37*37)
#define KDIM  384      // token dim
#define KV    65536    // voxels per batch
#define KPF   64       // per-voxel feature dim
#define KHID  256      // hidden
#define KOUT  16       // output
#define KGRID 37
#define KGV   (KB*KV)  // 131072 total voxels

typedef unsigned long long u64;

// packed fp32x2 FMA: d = a*b + d  (per 32-bit lane)
#define FMA2(d, a, b) asm("fma.rn.f32x2 %0, %1, %2, %0;" : "+l"(d) : "l"(a), "l"(b))
#define PACK2(d, s)   asm("mov.b64 %0, {%1, %1};" : "=l"(d) : "f"(s))

__device__ __forceinline__ float2 unpack2(u64 x) {
    float2 r; memcpy(&r, &x, 8); return r;
}

// ---------------- device scratch (no allocations allowed) -------------
__device__ float g_mean[KB*KM*KDIM];   // [2738][384]  mean over views
__device__ float g_T[KB*KM*KHID];      // [2738][256]  mean_tokens @ W1[64:] + b1

// =======================================================================
// Kernel A: mean over views.  patch_tokens [B, NV, M, DIM] -> g_mean
// =======================================================================
__global__ void mean_kernel(const float* __restrict__ pt) {
    int i = blockIdx.x * blockDim.x + threadIdx.x;     // float4 index
    const int total4 = KB * KM * KDIM / 4;
    if (i >= total4) return;
    const int dq = i % (KDIM / 4);
    const int bm = i / (KDIM / 4);
    const int b = bm / KM;
    const int m = bm % KM;
    const float4* base = (const float4*)pt;
    float4 s = make_float4(0.f, 0.f, 0.f, 0.f);
#pragma unroll
    for (int vw = 0; vw < KNV; vw++) {
        float4 x = base[((size_t)(b * KNV + vw) * KM + m) * (KDIM / 4) + dq];
        s.x += x.x; s.y += x.y; s.z += x.z; s.w += x.w;
    }
    const float inv = 1.0f / KNV;
    s.x *= inv; s.y *= inv; s.z *= inv; s.w *= inv;
    ((float4*)g_mean)[i] = s;
}

// =======================================================================
// Kernel B: table GEMM  g_T[r, j] = sum_k g_mean[r,k] * W1[64+k, j] + b1[j]
// packed f32x2 along j.
// =======================================================================
#define TBM 32
#define TBN 64
#define TBK 16
__global__ void table_kernel(const float* __restrict__ W1,
                             const float* __restrict__ b1) {
    __shared__ float As[TBK][TBM + 1];
    __shared__ float Bs[TBK][TBN];
    const int ROWS = KB * KM;                 // 2738
    const int t  = threadIdx.x;
    const int m0 = blockIdx.x * TBM;
    const int j0 = blockIdx.y * TBN;
    const int ty = t >> 4;                    // 0..15 -> 2 rows each
    const int tx = t & 15;                    // 0..15 -> 4 cols each

    u64 acc2[2][2] = {};

    for (int k0 = 0; k0 < KDIM; k0 += TBK) {
        {
            int idx = t * 2;
            int m  = idx / TBK;
            int kk = idx % TBK;               // even
            float2 v = make_float2(0.f, 0.f);
            if (m0 + m < ROWS)
                v = *(const float2*)&g_mean[(size_t)(m0 + m) * KDIM + k0 + kk];
            As[kk][m]     = v.x;
            As[kk + 1][m] = v.y;
        }
        {
            int kk = t >> 4;
            int jq = (t & 15) * 4;
            *(float4*)&Bs[kk][jq] =
                *(const float4*)&W1[(size_t)(KPF + k0 + kk) * KHID + j0 + jq];
        }
        __syncthreads();
#pragma unroll
        for (int kk = 0; kk < TBK; kk++) {
            float a0 = As[kk][ty * 2 + 0];
            float a1 = As[kk][ty * 2 + 1];
            u64 pa0, pa1;
            PACK2(pa0, a0); PACK2(pa1, a1);
            ulonglong2 bv = *(const ulonglong2*)&Bs[kk][tx * 4];
            FMA2(acc2[0][0], pa0, bv.x); FMA2(acc2[0][1], pa0, bv.y);
            FMA2(acc2[1][0], pa1, bv.x); FMA2(acc2[1][1], pa1, bv.y);
        }
        __syncthreads();
    }

    float4 bb = *(const float4*)&b1[j0 + tx * 4];
#pragma unroll
    for (int i = 0; i < 2; i++) {
        int r = m0 + ty * 2 + i;
        if (r < ROWS) {
            float2 lo = unpack2(acc2[i][0]);
            float2 hi = unpack2(acc2[i][1]);
            float4 o;
            o.x = lo.x + bb.x; o.y = lo.y + bb.y;
            o.z = hi.x + bb.z; o.w = hi.y + bb.w;
            *(float4*)&g_T[(size_t)r * KHID + j0 + tx * 4] = o;
        }
    }
}

// =======================================================================
// Kernel C: fused main kernel. Per block: 64 voxels, 256 threads.
// GEMM1 uses packed f32x2 FMAs: A (voxel feats) replicated pairwise in
// shared so {a,a} pairs load directly; B pairs along j come from float4.
// Shared layout (floats):
//   [0, 16640)          W1s [64][256]   (union Hs [64][260])
//   [AS2_OFF, +64*132)  As2 [64][132]   As2[k][2v]=As2[k][2v+1]=vf[v][k]
//   [W2_OFF, +4096)     W2s [256][16]
//   [IDX_OFF, +64)      sIdx[64]
// =======================================================================
#define VB 64
#define HS_STRIDE 260
#define AS2_STRIDE 132
#define AS2_OFF   16640
#define W2_OFF    (AS2_OFF + 64*AS2_STRIDE)     // 25088
#define IDX_OFF   (W2_OFF + 4096)               // 29184
#define SMEMC_FLOATS (IDX_OFF + 64)             // 29248
#define SMEMC_BYTES  (SMEMC_FLOATS * 4)         // 116992

__global__ void __launch_bounds__(256, 1)
fused_kernel(const float* __restrict__ vf, const float* __restrict__ vc,
             const float* __restrict__ Km, const float* __restrict__ Rt,
             const float* __restrict__ W1, const float* __restrict__ W2,
             const float* __restrict__ b2, float* __restrict__ out) {
    extern __shared__ float sm[];
    float* W1s = sm;                       // [64][256]
    float* Hs  = sm;                       // [64][260] (after GEMM1 sync)
    float* As2 = sm + AS2_OFF;             // [64][132] replicated pairs
    float* W2s = sm + W2_OFF;              // [256][16]
    int*   sIdx = (int*)(sm + IDX_OFF);    // [64]

    const int t  = threadIdx.x;
    const int g0 = blockIdx.x * VB;

    // ---- stage W1 top-64 rows: first 4096 float4 of W1 ----
    {
        const float4* src = (const float4*)W1;
        float4* dst = (float4*)W1s;
#pragma unroll
        for (int r = 0; r < 16; r++) dst[t + r * 256] = src[t + r * 256];
    }
    // ---- stage W2 [256][16] = 1024 float4 ----
    {
        const float4* src = (const float4*)W2;
        float4* dst = (float4*)W2s;
#pragma unroll
        for (int r = 0; r < 4; r++) dst[t + r * 256] = src[t + r * 256];
    }
    // ---- stage voxel features transposed + pairwise replicated ----
    {
#pragma unroll
        for (int r = 0; r < 16; r++) {
            int i = t + r * 256;           // 0..4095
            int v = i >> 6;
            int k = i & 63;
            float x = vf[((size_t)(g0 + v)) * KPF + k];
            *(float2*)&As2[k * AS2_STRIDE + 2 * v] = make_float2(x, x);
        }
    }
    // ---- projection -> token index (includes batch offset) ----
    if (t < VB) {
        int g = g0 + t;
        int b = g >> 16;                   // KV = 65536
        const float* c = vc + (size_t)g * 3;
        float x = c[0], y = c[1], z = c[2];
        float cam0 = Rt[0] * x + Rt[1] * y + Rt[2]  * z + Rt[3];
        float cam1 = Rt[4] * x + Rt[5] * y + Rt[6]  * z + Rt[7];
        float cam2 = Rt[8] * x + Rt[9] * y + Rt[10] * z + Rt[11];
        float p0 = Km[0] * cam0 + Km[1] * cam1 + Km[2] * cam2;
        float p1 = Km[3] * cam0 + Km[4] * cam1 + Km[5] * cam2;
        float p2 = Km[6] * cam0 + Km[7] * cam1 + Km[8] * cam2;
        float denom = p2 + 1e-6f;
        float u  = __fdiv_rn(p0, denom) * (float)(518.0 / 600.0);
        float vv = __fdiv_rn(p1, denom) * (float)(518.0 / 900.0);
        int px = (int)__fdiv_rn(u, 14.0f);      // truncate toward zero
        int py = (int)__fdiv_rn(vv, 14.0f);
        px = min(max(px, 0), KGRID - 1);
        py = min(max(py, 0), KGRID - 1);
        sIdx[t] = b * KM + px * KGRID + py;
    }
    __syncthreads();

    // ---- GEMM1 (packed): acc2[i][jp] += {a,a}[i] * {b,b+1}[jp] ----
    const int tx = t & 31;                 // 32 col groups of 8
    const int ty = t >> 5;                 // 8 voxel groups of 8
    const int jc = tx * 8;
    const int vr = ty * 8;
    u64 acc2[8][4] = {};                   // 8 voxels x 4 j-pairs
#pragma unroll 4
    for (int k = 0; k < 64; k++) {
        const float* arow = As2 + k * AS2_STRIDE + vr * 2;
        const float* brow = W1s + k * 256 + jc;
        ulonglong2 b01 = *(const ulonglong2*)brow;
        ulonglong2 b23 = *(const ulonglong2*)(brow + 4);
        ulonglong2 a01 = *(const ulonglong2*)arow;
        ulonglong2 a23 = *(const ulonglong2*)(arow + 4);
        ulonglong2 a45 = *(const ulonglong2*)(arow + 8);
        ulonglong2 a67 = *(const ulonglong2*)(arow + 12);
        u64 ap[8] = {a01.x, a01.y, a23.x, a23.y, a45.x, a45.y, a67.x, a67.y};
#pragma unroll
        for (int i = 0; i < 8; i++) {
            FMA2(acc2[i][0], ap[i], b01.x);
            FMA2(acc2[i][1], ap[i], b01.y);
            FMA2(acc2[i][2], ap[i], b23.x);
            FMA2(acc2[i][3], ap[i], b23.y);
        }
    }
    __syncthreads();   // everyone done reading W1s before it becomes Hs

    // ---- epilogue: + gathered T row, relu, stage into Hs ----
#pragma unroll
    for (int i = 0; i < 8; i++) {
        int row = sIdx[vr + i];
        const float* trow = g_T + (size_t)row * KHID + jc;
        float4 t0 = *(const float4*)trow;
        float4 t1 = *(const float4*)(trow + 4);
        float2 a0 = unpack2(acc2[i][0]);
        float2 a1 = unpack2(acc2[i][1]);
        float2 a2 = unpack2(acc2[i][2]);
        float2 a3 = unpack2(acc2[i][3]);
        float4 h0, h1;
        h0.x = fmaxf(a0.x + t0.x, 0.f);
        h0.y = fmaxf(a0.y + t0.y, 0.f);
        h0.z = fmaxf(a1.x + t0.z, 0.f);
        h0.w = fmaxf(a1.y + t0.w, 0.f);
        h1.x = fmaxf(a2.x + t1.x, 0.f);
        h1.y = fmaxf(a2.y + t1.y, 0.f);
        h1.z = fmaxf(a3.x + t1.z, 0.f);
        h1.w = fmaxf(a3.y + t1.w, 0.f);
        *(float4*)(Hs + (vr + i) * HS_STRIDE + jc)     = h0;
        *(float4*)(Hs + (vr + i) * HS_STRIDE + jc + 4) = h1;
    }
    __syncthreads();

    // ---- GEMM2: out[v2, og..og+3] = Hs[v2,:] @ W2[:, og..og+3] + b2 ----
    const int v2 = t >> 2;                 // 0..63
    const int og = (t & 3) * 4;            // 0,4,8,12
    float4 bv = *(const float4*)(b2 + og);
    float o0 = bv.x, o1 = bv.y, o2 = bv.z, o3 = bv.w;
    const float4* hrow = (const float4*)(Hs + v2 * HS_STRIDE);
#pragma unroll 4
    for (int k4 = 0; k4 < 64; k4++) {
        float4 h4 = hrow[k4];
        float4 w0 = *(const float4*)(W2s + (k4 * 4 + 0) * KOUT + og);
        float4 w1 = *(const float4*)(W2s + (k4 * 4 + 1) * KOUT + og);
        float4 w2 = *(const float4*)(W2s + (k4 * 4 + 2) * KOUT + og);
        float4 w3 = *(const float4*)(W2s + (k4 * 4 + 3) * KOUT + og);
        o0 += h4.x * w0.x + h4.y * w1.x + h4.z * w2.x + h4.w * w3.x;
        o1 += h4.x * w0.y + h4.y * w1.y + h4.z * w2.y + h4.w * w3.y;
        o2 += h4.x * w0.z + h4.y * w1.z + h4.z * w2.z + h4.w * w3.z;
        o3 += h4.x * w0.w + h4.y * w1.w + h4.z * w2.w + h4.w * w3.w;
    }
    float4 o = make_float4(o0, o1, o2, o3);
    *(float4*)(out + ((size_t)(g0 + v2)) * KOUT + og) = o;
}

// =======================================================================
extern "C" void kernel_launch(void* const* d_in, const int* in_sizes, int n_in,
                              void* d_out, int out_size) {
    (void)in_sizes; (void)n_in; (void)out_size;
    const float* pt = (const float*)d_in[0];
    const float* vf = (const float*)d_in[1];
    const float* vc = (const float*)d_in[2];
    const float* Km = (const float*)d_in[3];
    const float* Rt = (const float*)d_in[4];
    const float* W1 = (const float*)d_in[5];
    const float* b1 = (const float*)d_in[6];
    const float* W2 = (const float*)d_in[7];
    const float* b2 = (const float*)d_in[8];
    float* out = (float*)d_out;

    const int total4 = KB * KM * KDIM / 4;
    mean_kernel<<<(total4 + 255) / 256, 256>>>(pt);

    dim3 gridB((KB * KM + TBM - 1) / TBM, KHID / TBN);   // (86, 4)
    table_kernel<<<gridB, 256>>>(W1, b1);

    cudaFuncSetAttribute(fused_kernel,
                         cudaFuncAttributeMaxDynamicSharedMemorySize,
                         SMEMC_BYTES);
    fused_kernel<<<KGV / VB, 256, SMEMC_BYTES>>>(vf, vc, Km, Rt, W1, W2, b2, out);
}

// round 4
// speedup vs baseline: 2.0415x; 2.0415x over previous
#include <cuda_runtime.h>
#include <cuda_bf16.h>
#include <cstdint>
#include <string.h>

// ---------------- problem constants ----------------
#define KB    2
#define KNV   6
#define KM    1369
#define KDIM  384
#define KV    65536
#define KPF   64
#define KHID  256
#define KOUT  16
#define KGRID 37
#define KGV   (KB*KV)

// ---------------- device scratch ----------------
__device__ float g_mean[KB*KM*KDIM];
__device__ float g_T[KB*KM*KHID];          // token table fp32 (incl b1)
__device__ unsigned char g_B1[65536];      // W1top^T bf16 hi|lo, swizzled [256 rows][256B]
__device__ unsigned char g_B2[16384];      // W2^T    bf16 hi|lo, swizzled [16 rows][1024B]

// ---------------- helpers ----------------
__device__ __forceinline__ uint32_t smem_u32(const void* p) {
    uint32_t a;
    asm("{ .reg .u64 t; cvta.to.shared.u64 t, %1; cvt.u32.u64 %0, t; }" : "=r"(a) : "l"(p));
    return a;
}
__device__ __forceinline__ void ldsm4(uint32_t a, uint32_t* r) {
    asm volatile("ldmatrix.sync.aligned.m8n8.x4.shared.b16 {%0,%1,%2,%3}, [%4];"
        : "=r"(r[0]), "=r"(r[1]), "=r"(r[2]), "=r"(r[3]) : "r"(a));
}
__device__ __forceinline__ void ldsm2(uint32_t a, uint32_t* r) {
    asm volatile("ldmatrix.sync.aligned.m8n8.x2.shared.b16 {%0,%1}, [%2];"
        : "=r"(r[0]), "=r"(r[1]) : "r"(a));
}
__device__ __forceinline__ void mma16816(float* c, const uint32_t* a, const uint32_t* b) {
    asm volatile("mma.sync.aligned.m16n8k16.row.col.f32.bf16.bf16.f32 "
        "{%0,%1,%2,%3}, {%4,%5,%6,%7}, {%8,%9}, {%0,%1,%2,%3};"
        : "+f"(c[0]), "+f"(c[1]), "+f"(c[2]), "+f"(c[3])
        : "r"(a[0]), "r"(a[1]), "r"(a[2]), "r"(a[3]), "r"(b[0]), "r"(b[1]));
}
#define MBAR_INIT(a, n) asm volatile("mbarrier.init.shared.b64 [%0], %1;" :: "r"(a), "r"(n) : "memory")
#define MBAR_EXPECT(a, b) asm volatile("mbarrier.arrive.expect_tx.shared.b64 _, [%0], %1;" :: "r"(a), "r"(b) : "memory")
#define MBAR_WAIT(a, ph) do { \
    uint32_t _m = (a), _p = (ph), _d; \
    asm volatile("{ .reg .pred p; mbarrier.try_wait.parity.shared.b64 p, [%1], %2; selp.b32 %0,1,0,p; }" \
        : "=r"(_d) : "r"(_m), "r"(_p) : "memory"); \
    if (!_d) { \
        asm volatile("{ .reg .pred P1;\nWL_%=:\n mbarrier.try_wait.parity.shared.b64 P1, [%0], %1;\n @P1 bra.uni WD_%=;\n bra.uni WL_%=;\nWD_%=:\n}" \
            :: "r"(_m), "r"(_p) : "memory"); \
    } } while (0)
#define CP_BULK(dst, src, bytes, mbar) \
    asm volatile("cp.async.bulk.shared::cta.global.mbarrier::complete_tx::bytes [%0], [%1], %2, [%3];" \
        :: "r"(dst), "l"(src), "r"(bytes), "r"(mbar) : "memory")

// swizzled byte offset inside a row: granule16 g -> g ^ (row&7)
__device__ __forceinline__ uint32_t swz(int row, int kb, int rowbytes) {
    uint32_t g = (uint32_t)(kb >> 4);
    return (uint32_t)row * rowbytes + (((g ^ (row & 7))) << 4) + (kb & 15);
}

// =======================================================================
// Kernel A: mean over views
// =======================================================================
__global__ void mean_kernel(const float* __restrict__ pt) {
    int i = blockIdx.x * blockDim.x + threadIdx.x;
    const int total4 = KB * KM * KDIM / 4;
    if (i >= total4) return;
    const int dq = i % (KDIM / 4);
    const int bm = i / (KDIM / 4);
    const int b = bm / KM;
    const int m = bm % KM;
    const float4* base = (const float4*)pt;
    float4 s = make_float4(0.f, 0.f, 0.f, 0.f);
#pragma unroll
    for (int vw = 0; vw < KNV; vw++) {
        float4 x = base[((size_t)(b * KNV + vw) * KM + m) * (KDIM / 4) + dq];
        s.x += x.x; s.y += x.y; s.z += x.z; s.w += x.w;
    }
    const float inv = 1.0f / KNV;
    s.x *= inv; s.y *= inv; s.z *= inv; s.w *= inv;
    ((float4*)g_mean)[i] = s;
}

// =======================================================================
// Kernel B: table GEMM (fp32)  g_T = g_mean @ W1[64:] + b1
// =======================================================================
#define TBM 32
#define TBN 64
#define TBK 16
__global__ void table_kernel(const float* __restrict__ W1,
                             const float* __restrict__ b1) {
    __shared__ float As[TBK][TBM + 1];
    __shared__ float Bs[TBK][TBN];
    const int ROWS = KB * KM;
    const int t  = threadIdx.x;
    const int m0 = blockIdx.x * TBM;
    const int j0 = blockIdx.y * TBN;
    const int ty = t >> 4;
    const int tx = t & 15;
    float acc[2][4] = {};
    for (int k0 = 0; k0 < KDIM; k0 += TBK) {
        {
            int idx = t * 2;
            int m  = idx / TBK;
            int kk = idx % TBK;
            float2 v = make_float2(0.f, 0.f);
            if (m0 + m < ROWS)
                v = *(const float2*)&g_mean[(size_t)(m0 + m) * KDIM + k0 + kk];
            As[kk][m] = v.x;
            As[kk + 1][m] = v.y;
        }
        {
            int kk = t >> 4;
            int jq = (t & 15) * 4;
            *(float4*)&Bs[kk][jq] = *(const float4*)&W1[(size_t)(KPF + k0 + kk) * KHID + j0 + jq];
        }
        __syncthreads();
#pragma unroll
        for (int kk = 0; kk < TBK; kk++) {
            float a0 = As[kk][ty * 2 + 0];
            float a1 = As[kk][ty * 2 + 1];
            float4 b4 = *(const float4*)&Bs[kk][tx * 4];
            acc[0][0] += a0 * b4.x; acc[0][1] += a0 * b4.y;
            acc[0][2] += a0 * b4.z; acc[0][3] += a0 * b4.w;
            acc[1][0] += a1 * b4.x; acc[1][1] += a1 * b4.y;
            acc[1][2] += a1 * b4.z; acc[1][3] += a1 * b4.w;
        }
        __syncthreads();
    }
    float4 bb = *(const float4*)&b1[j0 + tx * 4];
#pragma unroll
    for (int i = 0; i < 2; i++) {
        int r = m0 + ty * 2 + i;
        if (r < ROWS) {
            float4 o;
            o.x = acc[i][0] + bb.x; o.y = acc[i][1] + bb.y;
            o.z = acc[i][2] + bb.z; o.w = acc[i][3] + bb.w;
            *(float4*)&g_T[(size_t)r * KHID + j0 + tx * 4] = o;
        }
    }
}

// =======================================================================
// Kernel P: split weights into bf16 hi/lo, swizzled operand layouts
//   g_B1: row n (0..255), k<64 hi at bytes 2k, lo at 128+2k   (rowbytes 256)
//   g_B2: row o (0..15),  k<256 hi at bytes 2k, lo at 512+2k  (rowbytes 1024)
// =======================================================================
__global__ void prep_kernel(const float* __restrict__ W1,
                            const float* __restrict__ W2) {
    int i = blockIdx.x * blockDim.x + threadIdx.x;
    if (i < 256 * 64) {
        int n = i >> 6, k = i & 63;
        float w = W1[(size_t)k * KHID + n];
        __nv_bfloat16 hi = __float2bfloat16_rn(w);
        __nv_bfloat16 lo = __float2bfloat16_rn(w - __bfloat162float(hi));
        *(__nv_bfloat16*)(g_B1 + swz(n, 2 * k, 256)) = hi;
        *(__nv_bfloat16*)(g_B1 + swz(n, 128 + 2 * k, 256)) = lo;
    } else if (i < 256 * 64 + 16 * 256) {
        int ii = i - 256 * 64;
        int o = ii >> 8, k = ii & 255;
        float w = W2[(size_t)k * KOUT + o];
        __nv_bfloat16 hi = __float2bfloat16_rn(w);
        __nv_bfloat16 lo = __float2bfloat16_rn(w - __bfloat162float(hi));
        *(__nv_bfloat16*)(g_B2 + swz(o, 2 * k, 1024)) = hi;
        *(__nv_bfloat16*)(g_B2 + swz(o, 512 + 2 * k, 1024)) = lo;
    }
}

// =======================================================================
// Kernel C: fused mma.sync kernel. 64 voxels / block, 256 threads (8 warps).
//   GEMM1: [64,256] = splitK-concat bf16 mma over K=192-equiv
//   epilogue: +gather(g_T) relu, bf16 hi/lo -> A2 smem
//   GEMM2: [64,16]  = splitK-concat bf16 mma over K=768-equiv
// SMEM layout (bytes):
//   A1 [64r][256B]  at 0       (16 KB)   (voxel feats hi|lo)
//   B1 [256r][256B] at 16384   (64 KB)
//   A2 [64r][1024B] at 0       (64 KB, reuses A1+B1 after GEMM1)
//   B2 [16r][1024B] at 81920   (16 KB)
//   sIdx[64] int    at 98304
//   mbar            at 98560
// =======================================================================
#define OFF_A1   0u
#define OFF_B1   16384u
#define OFF_A2   0u
#define OFF_B2   81920u
#define OFF_SIDX 98304u
#define OFF_MBAR 98560u
#define SMEMC_BYTES 98816u
#define VB 64

__global__ void __launch_bounds__(256, 2)
fused_kernel(const float* __restrict__ vf, const float* __restrict__ vc,
             const float* __restrict__ Km, const float* __restrict__ Rt,
             const float* __restrict__ b2, float* __restrict__ out) {
    extern __shared__ char smc[];
    const uint32_t sb = smem_u32(smc);
    const int t = threadIdx.x;
    const int l = t & 31;
    const int wid = t >> 5;
    const int g0 = blockIdx.x * VB;
    int* sIdx = (int*)(smc + OFF_SIDX);

    // ---- kick off weight bulk copies ----
    if (t == 0) {
        MBAR_INIT(sb + OFF_MBAR, 1);
        MBAR_EXPECT(sb + OFF_MBAR, 81920u);
        CP_BULK(sb + OFF_B1, (const void*)g_B1, 65536u, sb + OFF_MBAR);
        CP_BULK(sb + OFF_B2, (const void*)g_B2, 16384u, sb + OFF_MBAR);
    }

    // ---- stage A1: vf[64][64] fp32 -> bf16 hi(bytes 2k) / lo(128+2k) ----
    {
        const float4* vsrc = (const float4*)(vf + (size_t)g0 * KPF);
#pragma unroll
        for (int it = 0; it < 4; it++) {
            int idx = t + it * 256;        // 0..1023
            int r  = idx >> 4;
            int k4 = idx & 15;             // float4 chunk -> cols 4k4..4k4+3
            float4 x = vsrc[idx];
            __nv_bfloat162 h0 = __floats2bfloat162_rn(x.x, x.y);
            __nv_bfloat162 h1 = __floats2bfloat162_rn(x.z, x.w);
            __nv_bfloat162 l0 = __floats2bfloat162_rn(x.x - __low2float(h0), x.y - __high2float(h0));
            __nv_bfloat162 l1 = __floats2bfloat162_rn(x.z - __low2float(h1), x.w - __high2float(h1));
            uint2 hp, lp;
            memcpy(&hp.x, &h0, 4); memcpy(&hp.y, &h1, 4);
            memcpy(&lp.x, &l0, 4); memcpy(&lp.y, &l1, 4);
            *(uint2*)(smc + OFF_A1 + swz(r, 8 * k4, 256)) = hp;
            *(uint2*)(smc + OFF_A1 + swz(r, 128 + 8 * k4, 256)) = lp;
        }
    }
    // ---- projection -> token row index ----
    if (t < VB) {
        int g = g0 + t;
        int b = g >> 16;
        const float* c = vc + (size_t)g * 3;
        float x = c[0], y = c[1], z = c[2];
        float cam0 = Rt[0] * x + Rt[1] * y + Rt[2]  * z + Rt[3];
        float cam1 = Rt[4] * x + Rt[5] * y + Rt[6]  * z + Rt[7];
        float cam2 = Rt[8] * x + Rt[9] * y + Rt[10] * z + Rt[11];
        float p0 = Km[0] * cam0 + Km[1] * cam1 + Km[2] * cam2;
        float p1 = Km[3] * cam0 + Km[4] * cam1 + Km[5] * cam2;
        float p2 = Km[6] * cam0 + Km[7] * cam1 + Km[8] * cam2;
        float denom = p2 + 1e-6f;
        float u  = __fdiv_rn(p0, denom) * (float)(518.0 / 600.0);
        float vv = __fdiv_rn(p1, denom) * (float)(518.0 / 900.0);
        int px = (int)__fdiv_rn(u, 14.0f);
        int py = (int)__fdiv_rn(vv, 14.0f);
        px = min(max(px, 0), KGRID - 1);
        py = min(max(py, 0), KGRID - 1);
        sIdx[t] = b * KM + px * KGRID + py;
    }
    __syncthreads();
    MBAR_WAIT(sb + OFF_MBAR, 0);

    // ---- GEMM1: warp tile 32m x 64n; 12 k-steps (Ah*Bh, Al*Bh, Ah*Bl) ----
    const int wm = wid & 1, wn = wid >> 1;
    const int mrow = wm * 32, ncol = wn * 64;
    const int aRow = (l & 7) + ((l >> 3) & 1) * 8;   // row-in-16 for x4
    const int aG   = l >> 4;                          // k granule add for A x4
    const int bRow = ((l >> 4) << 3) + (l & 7);       // row-in-16 for B x4 (2 n-tiles)
    const int bG   = (l >> 3) & 1;

    float acc[2][8][4];
#pragma unroll
    for (int a = 0; a < 2; a++)
#pragma unroll
        for (int b_ = 0; b_ < 8; b_++)
#pragma unroll
            for (int q = 0; q < 4; q++) acc[a][b_][q] = 0.f;

#pragma unroll
    for (int s = 0; s < 12; s++) {
        const int ph = s >> 2, ks = s & 3;
        const int a_kb = (ph == 1 ? 128 : 0) + ks * 32;
        const int b_kb = (ph == 2 ? 128 : 0) + ks * 32;
        uint32_t af[2][4];
#pragma unroll
        for (int mt = 0; mt < 2; mt++) {
            int row = mrow + mt * 16 + aRow;
            uint32_t addr = sb + OFF_A1 + (uint32_t)row * 256u +
                            (((((a_kb >> 4) + aG)) ^ (row & 7)) << 4);
            ldsm4(addr, af[mt]);
        }
#pragma unroll
        for (int np = 0; np < 4; np++) {
            int row = ncol + np * 16 + bRow;
            uint32_t addr = sb + OFF_B1 + (uint32_t)row * 256u +
                            ((((b_kb >> 4) + bG) ^ (row & 7)) << 4);
            uint32_t bf[4];
            ldsm4(addr, bf);
#pragma unroll
            for (int mt = 0; mt < 2; mt++) {
                mma16816(acc[mt][np * 2 + 0], af[mt], bf);
                mma16816(acc[mt][np * 2 + 1], af[mt], bf + 2);
            }
        }
    }
    __syncthreads();   // all warps done reading A1/B1

    // ---- epilogue: + gather, relu, bf16 split -> A2 ----
    {
        const int rb = l >> 2, cq = (l & 3) * 2;
#pragma unroll
        for (int mt = 0; mt < 2; mt++) {
            int r0 = mrow + mt * 16 + rb;
            int r1 = r0 + 8;
            const float* T0 = g_T + (size_t)sIdx[r0] * KHID;
            const float* T1 = g_T + (size_t)sIdx[r1] * KHID;
#pragma unroll
            for (int nt = 0; nt < 8; nt++) {
                int c0 = ncol + nt * 8 + cq;
                float2 t0 = *(const float2*)(T0 + c0);
                float2 t1 = *(const float2*)(T1 + c0);
                float h00 = fmaxf(acc[mt][nt][0] + t0.x, 0.f);
                float h01 = fmaxf(acc[mt][nt][1] + t0.y, 0.f);
                float h10 = fmaxf(acc[mt][nt][2] + t1.x, 0.f);
                float h11 = fmaxf(acc[mt][nt][3] + t1.y, 0.f);
                __nv_bfloat162 hA = __floats2bfloat162_rn(h00, h01);
                __nv_bfloat162 hB = __floats2bfloat162_rn(h10, h11);
                __nv_bfloat162 lA = __floats2bfloat162_rn(h00 - __low2float(hA), h01 - __high2float(hA));
                __nv_bfloat162 lB = __floats2bfloat162_rn(h10 - __low2float(hB), h11 - __high2float(hB));
                uint32_t uhA, uhB, ulA, ulB;
                memcpy(&uhA, &hA, 4); memcpy(&uhB, &hB, 4);
                memcpy(&ulA, &lA, 4); memcpy(&ulB, &lB, 4);
                uint32_t cb = (uint32_t)(c0 * 2);
                uint32_t g = cb >> 4, off = cb & 15;
                *(uint32_t*)(smc + OFF_A2 + (uint32_t)r0 * 1024u + ((g ^ (r0 & 7)) << 4) + off) = uhA;
                *(uint32_t*)(smc + OFF_A2 + (uint32_t)r1 * 1024u + ((g ^ (r1 & 7)) << 4) + off) = uhB;
                *(uint32_t*)(smc + OFF_A2 + (uint32_t)r0 * 1024u + (((g + 32) ^ (r0 & 7)) << 4) + off) = ulA;
                *(uint32_t*)(smc + OFF_A2 + (uint32_t)r1 * 1024u + (((g + 32) ^ (r1 & 7)) << 4) + off) = ulB;
            }
        }
    }
    __syncthreads();

    // ---- GEMM2: warp tile 16m x 8n, 48 k-steps (Hh*Wh, Hl*Wh, Hh*Wl) ----
    {
        const int wm2 = wid & 3, wn2 = wid >> 2;
        const int m2 = wm2 * 16, n2 = wn2 * 8;
        float d0[4] = {0.f, 0.f, 0.f, 0.f};
        float d1[4] = {0.f, 0.f, 0.f, 0.f};
#pragma unroll
        for (int s = 0; s < 48; s++) {
            const int ph = s >> 4, ks = s & 15;
            const int a_kb = (ph == 1 ? 512 : 0) + ks * 32;
            const int b_kb = (ph == 2 ? 512 : 0) + ks * 32;
            uint32_t af[4], bf[2];
            int row = m2 + aRow;
            uint32_t aaddr = sb + OFF_A2 + (uint32_t)row * 1024u +
                             ((((a_kb >> 4) + aG) ^ (row & 7)) << 4);
            ldsm4(aaddr, af);
            int brow = n2 + (l & 7);
            uint32_t baddr = sb + OFF_B2 + (uint32_t)brow * 1024u +
                             ((((b_kb >> 4) + bG) ^ (brow & 7)) << 4);
            ldsm2(baddr, bf);
            if (s & 1) mma16816(d1, af, bf);
            else       mma16816(d0, af, bf);
        }
        // ---- bias + store ----
        int r0 = m2 + (l >> 2), c0 = n2 + (l & 3) * 2;
        float2 bv = *(const float2*)(b2 + c0);
        float2 o0 = make_float2(d0[0] + d1[0] + bv.x, d0[1] + d1[1] + bv.y);
        float2 o1 = make_float2(d0[2] + d1[2] + bv.x, d0[3] + d1[3] + bv.y);
        *(float2*)(out + (size_t)(g0 + r0) * KOUT + c0) = o0;
        *(float2*)(out + (size_t)(g0 + r0 + 8) * KOUT + c0) = o1;
    }
}

// =======================================================================
extern "C" void kernel_launch(void* const* d_in, const int* in_sizes, int n_in,
                              void* d_out, int out_size) {
    (void)in_sizes; (void)n_in; (void)out_size;
    const float* pt = (const float*)d_in[0];
    const float* vf = (const float*)d_in[1];
    const float* vc = (const float*)d_in[2];
    const float* Km = (const float*)d_in[3];
    const float* Rt = (const float*)d_in[4];
    const float* W1 = (const float*)d_in[5];
    const float* b1 = (const float*)d_in[6];
    const float* W2 = (const float*)d_in[7];
    const float* b2 = (const float*)d_in[8];
    float* out = (float*)d_out;

    const int total4 = KB * KM * KDIM / 4;
    mean_kernel<<<(total4 + 255) / 256, 256>>>(pt);

    prep_kernel<<<(256 * 64 + 16 * 256 + 255) / 256, 256>>>(W1, W2);

    dim3 gridB((KB * KM + TBM - 1) / TBM, KHID / TBN);
    table_kernel<<<gridB, 256>>>(W1, b1);

    cudaFuncSetAttribute(fused_kernel,
                         cudaFuncAttributeMaxDynamicSharedMemorySize,
                         SMEMC_BYTES);
    fused_kernel<<<KGV / VB, 256, SMEMC_BYTES>>>(vf, vc, Km, Rt, b2, out);
}

// round 5
// speedup vs baseline: 2.2602x; 1.1072x over previous
#include <cuda_runtime.h>
#include <cuda_bf16.h>
#include <cstdint>
#include <string.h>

// ---------------- problem constants ----------------
#define KB    2
#define KNV   6
#define KM    1369
#define KDIM  384
#define KV    65536
#define KPF   64
#define KHID  256
#define KOUT  16
#define KGRID 37
#define KGV   (KB*KV)

// ---------------- device scratch ----------------
__device__ float g_mean[KB*KM*KDIM];
__device__ float g_T[KB*KM*KHID];          // token table fp32 (incl b1)
__device__ unsigned char g_B1[65536];      // W1top^T bf16 hi|lo, swizzled [256 rows][256B]
__device__ unsigned char g_B2[16384];      // W2^T    bf16 hi|lo, swizzled [16 rows][1024B]

// ---------------- helpers ----------------
__device__ __forceinline__ uint32_t smem_u32(const void* p) {
    uint32_t a;
    asm("{ .reg .u64 t; cvta.to.shared.u64 t, %1; cvt.u32.u64 %0, t; }" : "=r"(a) : "l"(p));
    return a;
}
__device__ __forceinline__ void ldsm4(uint32_t a, uint32_t* r) {
    asm volatile("ldmatrix.sync.aligned.m8n8.x4.shared.b16 {%0,%1,%2,%3}, [%4];"
        : "=r"(r[0]), "=r"(r[1]), "=r"(r[2]), "=r"(r[3]) : "r"(a));
}
__device__ __forceinline__ void mma16816(float* c, const uint32_t* a, const uint32_t* b) {
    asm volatile("mma.sync.aligned.m16n8k16.row.col.f32.bf16.bf16.f32 "
        "{%0,%1,%2,%3}, {%4,%5,%6,%7}, {%8,%9}, {%0,%1,%2,%3};"
        : "+f"(c[0]), "+f"(c[1]), "+f"(c[2]), "+f"(c[3])
        : "r"(a[0]), "r"(a[1]), "r"(a[2]), "r"(a[3]), "r"(b[0]), "r"(b[1]));
}
#define MBAR_INIT(a, n) asm volatile("mbarrier.init.shared.b64 [%0], %1;" :: "r"(a), "r"(n) : "memory")
#define MBAR_EXPECT(a, b) asm volatile("mbarrier.arrive.expect_tx.shared.b64 _, [%0], %1;" :: "r"(a), "r"(b) : "memory")
#define MBAR_WAIT(a, ph) do { \
    uint32_t _m = (a), _p = (ph), _d; \
    asm volatile("{ .reg .pred p; mbarrier.try_wait.parity.shared.b64 p, [%1], %2; selp.b32 %0,1,0,p; }" \
        : "=r"(_d) : "r"(_m), "r"(_p) : "memory"); \
    if (!_d) { \
        asm volatile("{ .reg .pred P1;\nWL_%=:\n mbarrier.try_wait.parity.shared.b64 P1, [%0], %1;\n @P1 bra.uni WD_%=;\n bra.uni WL_%=;\nWD_%=:\n}" \
            :: "r"(_m), "r"(_p) : "memory"); \
    } } while (0)
#define CP_BULK(dst, src, bytes, mbar) \
    asm volatile("cp.async.bulk.shared::cta.global.mbarrier::complete_tx::bytes [%0], [%1], %2, [%3];" \
        :: "r"(dst), "l"(src), "r"(bytes), "r"(mbar) : "memory")

// swizzled byte offset inside a row: granule16 g -> g ^ (row&7)
__device__ __forceinline__ uint32_t swz(int row, int kb, int rowbytes) {
    uint32_t g = (uint32_t)(kb >> 4);
    return (uint32_t)row * rowbytes + (((g ^ (row & 7))) << 4) + (kb & 15);
}

// =======================================================================
// Kernel A: mean over views
// =======================================================================
__global__ void mean_kernel(const float* __restrict__ pt) {
    int i = blockIdx.x * blockDim.x + threadIdx.x;
    const int total4 = KB * KM * KDIM / 4;
    if (i >= total4) return;
    const int dq = i % (KDIM / 4);
    const int bm = i / (KDIM / 4);
    const int b = bm / KM;
    const int m = bm % KM;
    const float4* base = (const float4*)pt;
    float4 s = make_float4(0.f, 0.f, 0.f, 0.f);
#pragma unroll
    for (int vw = 0; vw < KNV; vw++) {
        float4 x = base[((size_t)(b * KNV + vw) * KM + m) * (KDIM / 4) + dq];
        s.x += x.x; s.y += x.y; s.z += x.z; s.w += x.w;
    }
    const float inv = 1.0f / KNV;
    s.x *= inv; s.y *= inv; s.z *= inv; s.w *= inv;
    ((float4*)g_mean)[i] = s;
}

// =======================================================================
// Kernel B: table GEMM (fp32)  g_T = g_mean @ W1[64:] + b1
// =======================================================================
#define TBM 32
#define TBN 64
#define TBK 16
__global__ void table_kernel(const float* __restrict__ W1,
                             const float* __restrict__ b1) {
    __shared__ float As[TBK][TBM + 1];
    __shared__ float Bs[TBK][TBN];
    const int ROWS = KB * KM;
    const int t  = threadIdx.x;
    const int m0 = blockIdx.x * TBM;
    const int j0 = blockIdx.y * TBN;
    const int ty = t >> 4;
    const int tx = t & 15;
    float acc[2][4] = {};
    for (int k0 = 0; k0 < KDIM; k0 += TBK) {
        {
            int idx = t * 2;
            int m  = idx / TBK;
            int kk = idx % TBK;
            float2 v = make_float2(0.f, 0.f);
            if (m0 + m < ROWS)
                v = *(const float2*)&g_mean[(size_t)(m0 + m) * KDIM + k0 + kk];
            As[kk][m] = v.x;
            As[kk + 1][m] = v.y;
        }
        {
            int kk = t >> 4;
            int jq = (t & 15) * 4;
            *(float4*)&Bs[kk][jq] = *(const float4*)&W1[(size_t)(KPF + k0 + kk) * KHID + j0 + jq];
        }
        __syncthreads();
#pragma unroll
        for (int kk = 0; kk < TBK; kk++) {
            float a0 = As[kk][ty * 2 + 0];
            float a1 = As[kk][ty * 2 + 1];
            float4 b4 = *(const float4*)&Bs[kk][tx * 4];
            acc[0][0] += a0 * b4.x; acc[0][1] += a0 * b4.y;
            acc[0][2] += a0 * b4.z; acc[0][3] += a0 * b4.w;
            acc[1][0] += a1 * b4.x; acc[1][1] += a1 * b4.y;
            acc[1][2] += a1 * b4.z; acc[1][3] += a1 * b4.w;
        }
        __syncthreads();
    }
    float4 bb = *(const float4*)&b1[j0 + tx * 4];
#pragma unroll
    for (int i = 0; i < 2; i++) {
        int r = m0 + ty * 2 + i;
        if (r < ROWS) {
            float4 o;
            o.x = acc[i][0] + bb.x; o.y = acc[i][1] + bb.y;
            o.z = acc[i][2] + bb.z; o.w = acc[i][3] + bb.w;
            *(float4*)&g_T[(size_t)r * KHID + j0 + tx * 4] = o;
        }
    }
}

// =======================================================================
// Kernel P: split weights into bf16 hi/lo, swizzled operand layouts
// =======================================================================
__global__ void prep_kernel(const float* __restrict__ W1,
                            const float* __restrict__ W2) {
    int i = blockIdx.x * blockDim.x + threadIdx.x;
    if (i < 256 * 64) {
        int n = i >> 6, k = i & 63;
        float w = W1[(size_t)k * KHID + n];
        __nv_bfloat16 hi = __float2bfloat16_rn(w);
        __nv_bfloat16 lo = __float2bfloat16_rn(w - __bfloat162float(hi));
        *(__nv_bfloat16*)(g_B1 + swz(n, 2 * k, 256)) = hi;
        *(__nv_bfloat16*)(g_B1 + swz(n, 128 + 2 * k, 256)) = lo;
    } else if (i < 256 * 64 + 16 * 256) {
        int ii = i - 256 * 64;
        int o = ii >> 8, k = ii & 255;
        float w = W2[(size_t)k * KOUT + o];
        __nv_bfloat16 hi = __float2bfloat16_rn(w);
        __nv_bfloat16 lo = __float2bfloat16_rn(w - __bfloat162float(hi));
        *(__nv_bfloat16*)(g_B2 + swz(o, 2 * k, 1024)) = hi;
        *(__nv_bfloat16*)(g_B2 + swz(o, 512 + 2 * k, 1024)) = lo;
    }
}

// =======================================================================
// Kernel C: fused mma.sync kernel. 64 voxels / block, 256 threads (8 warps).
//   GEMM1: [64,256] splitK-concat bf16 mma (12 k-steps)
//   epilogue: +gather(g_T), relu, bf16 split — ALL IN REGISTERS,
//             repacked directly as GEMM2 A-fragments (C-frag == A-frag layout)
//   GEMM2: per-warp partial [32x16] over its 64-wide k-slice, then
//          4-way smem reduction over k-slices.
// SMEM: A1 16KB @0, B1 64KB @16384, B2 16KB @81920, sIdx @98304, mbar @98560
//       P (reduction, 4x64x20 fl = 20KB) reuses @0 after GEMM1.
// =======================================================================
#define OFF_A1   0u
#define OFF_B1   16384u
#define OFF_B2   81920u
#define OFF_SIDX 98304u
#define OFF_MBAR 98560u
#define SMEMC_BYTES 98816u
#define VB 64
#define PSTRIDE 20

__global__ void __launch_bounds__(256, 2)
fused_kernel(const float* __restrict__ vf, const float* __restrict__ vc,
             const float* __restrict__ Km, const float* __restrict__ Rt,
             const float* __restrict__ b2, float* __restrict__ out) {
    extern __shared__ char smc[];
    const uint32_t sb = smem_u32(smc);
    const int t = threadIdx.x;
    const int l = t & 31;
    const int wid = t >> 5;
    const int g0 = blockIdx.x * VB;
    int* sIdx = (int*)(smc + OFF_SIDX);

    // ---- kick off weight bulk copies ----
    if (t == 0) {
        MBAR_INIT(sb + OFF_MBAR, 1);
        MBAR_EXPECT(sb + OFF_MBAR, 81920u);
        CP_BULK(sb + OFF_B1, (const void*)g_B1, 65536u, sb + OFF_MBAR);
        CP_BULK(sb + OFF_B2, (const void*)g_B2, 16384u, sb + OFF_MBAR);
    }

    // ---- stage A1: vf[64][64] fp32 -> bf16 hi(bytes 2k) / lo(128+2k) ----
    {
        const float4* vsrc = (const float4*)(vf + (size_t)g0 * KPF);
#pragma unroll
        for (int it = 0; it < 4; it++) {
            int idx = t + it * 256;
            int r  = idx >> 4;
            int k4 = idx & 15;
            float4 x = vsrc[idx];
            __nv_bfloat162 h0 = __floats2bfloat162_rn(x.x, x.y);
            __nv_bfloat162 h1 = __floats2bfloat162_rn(x.z, x.w);
            __nv_bfloat162 l0 = __floats2bfloat162_rn(x.x - __low2float(h0), x.y - __high2float(h0));
            __nv_bfloat162 l1 = __floats2bfloat162_rn(x.z - __low2float(h1), x.w - __high2float(h1));
            uint2 hp, lp;
            memcpy(&hp.x, &h0, 4); memcpy(&hp.y, &h1, 4);
            memcpy(&lp.x, &l0, 4); memcpy(&lp.y, &l1, 4);
            *(uint2*)(smc + OFF_A1 + swz(r, 8 * k4, 256)) = hp;
            *(uint2*)(smc + OFF_A1 + swz(r, 128 + 8 * k4, 256)) = lp;
        }
    }
    // ---- projection -> token row index ----
    if (t < VB) {
        int g = g0 + t;
        int b = g >> 16;
        const float* c = vc + (size_t)g * 3;
        float x = c[0], y = c[1], z = c[2];
        float cam0 = Rt[0] * x + Rt[1] * y + Rt[2]  * z + Rt[3];
        float cam1 = Rt[4] * x + Rt[5] * y + Rt[6]  * z + Rt[7];
        float cam2 = Rt[8] * x + Rt[9] * y + Rt[10] * z + Rt[11];
        float p0 = Km[0] * cam0 + Km[1] * cam1 + Km[2] * cam2;
        float p1 = Km[3] * cam0 + Km[4] * cam1 + Km[5] * cam2;
        float p2 = Km[6] * cam0 + Km[7] * cam1 + Km[8] * cam2;
        float denom = p2 + 1e-6f;
        float u  = __fdiv_rn(p0, denom) * (float)(518.0 / 600.0);
        float vv = __fdiv_rn(p1, denom) * (float)(518.0 / 900.0);
        int px = (int)__fdiv_rn(u, 14.0f);
        int py = (int)__fdiv_rn(vv, 14.0f);
        px = min(max(px, 0), KGRID - 1);
        py = min(max(py, 0), KGRID - 1);
        sIdx[t] = b * KM + px * KGRID + py;
    }
    __syncthreads();
    MBAR_WAIT(sb + OFF_MBAR, 0);

    // ---- GEMM1: warp tile 32m x 64n; 12 k-steps ----
    const int wm = wid & 1, wn = wid >> 1;
    const int mrow = wm * 32, ncol = wn * 64;
    const int aRow = (l & 7) + ((l >> 3) & 1) * 8;
    const int aG   = l >> 4;
    const int bRow = ((l >> 4) << 3) + (l & 7);
    const int bG   = (l >> 3) & 1;

    float acc[2][8][4];
#pragma unroll
    for (int a = 0; a < 2; a++)
#pragma unroll
        for (int b_ = 0; b_ < 8; b_++)
#pragma unroll
            for (int q = 0; q < 4; q++) acc[a][b_][q] = 0.f;

#pragma unroll
    for (int s = 0; s < 12; s++) {
        const int ph = s >> 2, ks = s & 3;
        const int a_kb = (ph == 1 ? 128 : 0) + ks * 32;
        const int b_kb = (ph == 2 ? 128 : 0) + ks * 32;
        uint32_t af[2][4];
#pragma unroll
        for (int mt = 0; mt < 2; mt++) {
            int row = mrow + mt * 16 + aRow;
            uint32_t addr = sb + OFF_A1 + (uint32_t)row * 256u +
                            (((((a_kb >> 4) + aG)) ^ (row & 7)) << 4);
            ldsm4(addr, af[mt]);
        }
#pragma unroll
        for (int np = 0; np < 4; np++) {
            int row = ncol + np * 16 + bRow;
            uint32_t addr = sb + OFF_B1 + (uint32_t)row * 256u +
                            ((((b_kb >> 4) + bG) ^ (row & 7)) << 4);
            uint32_t bf[4];
            ldsm4(addr, bf);
#pragma unroll
            for (int mt = 0; mt < 2; mt++) {
                mma16816(acc[mt][np * 2 + 0], af[mt], bf);
                mma16816(acc[mt][np * 2 + 1], af[mt], bf + 2);
            }
        }
    }

    // ---- epilogue IN REGISTERS: +gather, relu, bf16 split -> A2 frags ----
    // C-frag layout == A-frag layout: pack directly for GEMM2.
    uint32_t ah[2][4][4], al[2][4][4];
    {
        const int rb = l >> 2, cq = (l & 3) * 2;
#pragma unroll
        for (int mt = 0; mt < 2; mt++) {
            int r0 = mrow + mt * 16 + rb;
            int r1 = r0 + 8;
            const float* T0 = g_T + (size_t)sIdx[r0] * KHID;
            const float* T1 = g_T + (size_t)sIdx[r1] * KHID;
#pragma unroll
            for (int nt = 0; nt < 8; nt++) {
                int c0 = ncol + nt * 8 + cq;
                float2 t0 = *(const float2*)(T0 + c0);
                float2 t1 = *(const float2*)(T1 + c0);
                float h00 = fmaxf(acc[mt][nt][0] + t0.x, 0.f);
                float h01 = fmaxf(acc[mt][nt][1] + t0.y, 0.f);
                float h10 = fmaxf(acc[mt][nt][2] + t1.x, 0.f);
                float h11 = fmaxf(acc[mt][nt][3] + t1.y, 0.f);
                __nv_bfloat162 hA = __floats2bfloat162_rn(h00, h01);
                __nv_bfloat162 hB = __floats2bfloat162_rn(h10, h11);
                __nv_bfloat162 lA = __floats2bfloat162_rn(h00 - __low2float(hA), h01 - __high2float(hA));
                __nv_bfloat162 lB = __floats2bfloat162_rn(h10 - __low2float(hB), h11 - __high2float(hB));
                int kb = nt >> 1, hf = (nt & 1) * 2;
                memcpy(&ah[mt][kb][hf + 0], &hA, 4);
                memcpy(&ah[mt][kb][hf + 1], &hB, 4);
                memcpy(&al[mt][kb][hf + 0], &lA, 4);
                memcpy(&al[mt][kb][hf + 1], &lB, 4);
            }
        }
    }

    // ---- GEMM2: per-warp partial over k-slice [ncol, ncol+64) ----
    float d[2][2][4];
#pragma unroll
    for (int mt = 0; mt < 2; mt++)
#pragma unroll
        for (int j = 0; j < 2; j++)
#pragma unroll
            for (int q = 0; q < 4; q++) d[mt][j][q] = 0.f;

#pragma unroll
    for (int kb = 0; kb < 4; kb++) {
        int ghi = (ncol >> 3) + 2 * kb + bG;
        int glo = 32 + (ncol >> 3) + 2 * kb + bG;
        uint32_t bhf[4], blf[4];
        uint32_t ahi_addr = sb + OFF_B2 + (uint32_t)bRow * 1024u + (((uint32_t)(ghi ^ (bRow & 7))) << 4);
        uint32_t alo_addr = sb + OFF_B2 + (uint32_t)bRow * 1024u + (((uint32_t)(glo ^ (bRow & 7))) << 4);
        ldsm4(ahi_addr, bhf);
        ldsm4(alo_addr, blf);
#pragma unroll
        for (int mt = 0; mt < 2; mt++)
#pragma unroll
            for (int j = 0; j < 2; j++) {
                mma16816(d[mt][j], ah[mt][kb], bhf + j * 2);
                mma16816(d[mt][j], al[mt][kb], bhf + j * 2);
                mma16816(d[mt][j], ah[mt][kb], blf + j * 2);
            }
    }

    __syncthreads();   // all warps finished reading A1/B1 (region 0 reused as P)

    // ---- store partials P[wn][64][PSTRIDE] and reduce over wn ----
    {
        float* P = (float*)smc;
        const int rb = l >> 2, c2 = (l & 3) * 2;
#pragma unroll
        for (int mt = 0; mt < 2; mt++) {
            int r0 = mrow + mt * 16 + rb;
#pragma unroll
            for (int j = 0; j < 2; j++) {
                int cc = j * 8 + c2;
                *(float2*)&P[(wn * 64 + r0) * PSTRIDE + cc] = make_float2(d[mt][j][0], d[mt][j][1]);
                *(float2*)&P[(wn * 64 + r0 + 8) * PSTRIDE + cc] = make_float2(d[mt][j][2], d[mt][j][3]);
            }
        }
    }
    __syncthreads();
    {
        const float* P = (const float*)smc;
        int row = t >> 2;
        int cq = (t & 3) * 4;
        float4 s0 = *(const float4*)&P[(0 * 64 + row) * PSTRIDE + cq];
        float4 s1 = *(const float4*)&P[(1 * 64 + row) * PSTRIDE + cq];
        float4 s2 = *(const float4*)&P[(2 * 64 + row) * PSTRIDE + cq];
        float4 s3 = *(const float4*)&P[(3 * 64 + row) * PSTRIDE + cq];
        float4 bv = *(const float4*)(b2 + cq);
        float4 o;
        o.x = s0.x + s1.x + s2.x + s3.x + bv.x;
        o.y = s0.y + s1.y + s2.y + s3.y + bv.y;
        o.z = s0.z + s1.z + s2.z + s3.z + bv.z;
        o.w = s0.w + s1.w + s2.w + s3.w + bv.w;
        *(float4*)(out + (size_t)(g0 + row) * KOUT + cq) = o;
    }
}

// =======================================================================
extern "C" void kernel_launch(void* const* d_in, const int* in_sizes, int n_in,
                              void* d_out, int out_size) {
    (void)in_sizes; (void)n_in; (void)out_size;
    const float* pt = (const float*)d_in[0];
    const float* vf = (const float*)d_in[1];
    const float* vc = (const float*)d_in[2];
    const float* Km = (const float*)d_in[3];
    const float* Rt = (const float*)d_in[4];
    const float* W1 = (const float*)d_in[5];
    const float* b1 = (const float*)d_in[6];
    const float* W2 = (const float*)d_in[7];
    const float* b2 = (const float*)d_in[8];
    float* out = (float*)d_out;

    const int total4 = KB * KM * KDIM / 4;
    mean_kernel<<<(total4 + 255) / 256, 256>>>(pt);

    prep_kernel<<<(256 * 64 + 16 * 256 + 255) / 256, 256>>>(W1, W2);

    dim3 gridB((KB * KM + TBM - 1) / TBM, KHID / TBN);
    table_kernel<<<gridB, 256>>>(W1, b1);

    cudaFuncSetAttribute(fused_kernel,
                         cudaFuncAttributeMaxDynamicSharedMemorySize,
                         SMEMC_BYTES);
    fused_kernel<<<KGV / VB, 256, SMEMC_BYTES>>>(vf, vc, Km, Rt, b2, out);
}

// round 6
// speedup vs baseline: 2.6896x; 1.1900x over previous
#include <cuda_runtime.h>
#include <cuda_bf16.h>
#include <cstdint>
#include <string.h>

// ---------------- problem constants ----------------
#define KB    2
#define KNV   6
#define KM    1369
#define KDIM  384
#define KV    65536
#define KPF   64
#define KHID  256
#define KOUT  16
#define KGRID 37
#define KGV   (KB*KV)
#define ROWS_T (KB*KM)        // 2738
#define ROWS_PAD 2752         // 43*64

// ---------------- device scratch ----------------
__device__ float g_mean[KB*KM*KDIM];
__device__ float g_T[KB*KM*KHID];          // token table fp32 (incl b1)
__device__ unsigned char g_B1[65536];      // W1top^T bf16 hi|lo, swizzled [256r][256B]
__device__ unsigned char g_B2[16384];      // W2^T    bf16 hi|lo, swizzled [16r][1024B]
// W1bot^T bf16, 6 chunks of k64: chunk c: hi plane [256r][128B] then lo plane
__device__ unsigned char g_TB[6*2*32768];

// ---------------- helpers ----------------
__device__ __forceinline__ uint32_t smem_u32(const void* p) {
    uint32_t a;
    asm("{ .reg .u64 t; cvta.to.shared.u64 t, %1; cvt.u32.u64 %0, t; }" : "=r"(a) : "l"(p));
    return a;
}
__device__ __forceinline__ void ldsm4(uint32_t a, uint32_t* r) {
    asm volatile("ldmatrix.sync.aligned.m8n8.x4.shared.b16 {%0,%1,%2,%3}, [%4];"
        : "=r"(r[0]), "=r"(r[1]), "=r"(r[2]), "=r"(r[3]) : "r"(a));
}
__device__ __forceinline__ void mma16816(float* c, const uint32_t* a, const uint32_t* b) {
    asm volatile("mma.sync.aligned.m16n8k16.row.col.f32.bf16.bf16.f32 "
        "{%0,%1,%2,%3}, {%4,%5,%6,%7}, {%8,%9}, {%0,%1,%2,%3};"
        : "+f"(c[0]), "+f"(c[1]), "+f"(c[2]), "+f"(c[3])
        : "r"(a[0]), "r"(a[1]), "r"(a[2]), "r"(a[3]), "r"(b[0]), "r"(b[1]));
}
#define MBAR_INIT(a, n) asm volatile("mbarrier.init.shared.b64 [%0], %1;" :: "r"(a), "r"(n) : "memory")
#define MBAR_EXPECT(a, b) asm volatile("mbarrier.arrive.expect_tx.shared.b64 _, [%0], %1;" :: "r"(a), "r"(b) : "memory")
#define MBAR_WAIT(a, ph) do { \
    uint32_t _m = (a), _p = (ph), _d; \
    asm volatile("{ .reg .pred p; mbarrier.try_wait.parity.shared.b64 p, [%1], %2; selp.b32 %0,1,0,p; }" \
        : "=r"(_d) : "r"(_m), "r"(_p) : "memory"); \
    if (!_d) { \
        asm volatile("{ .reg .pred P1;\nWL_%=:\n mbarrier.try_wait.parity.shared.b64 P1, [%0], %1;\n @P1 bra.uni WD_%=;\n bra.uni WL_%=;\nWD_%=:\n}" \
            :: "r"(_m), "r"(_p) : "memory"); \
    } } while (0)
#define CP_BULK(dst, src, bytes, mbar) \
    asm volatile("cp.async.bulk.shared::cta.global.mbarrier::complete_tx::bytes [%0], [%1], %2, [%3];" \
        :: "r"(dst), "l"(src), "r"(bytes), "r"(mbar) : "memory")

// swizzled byte offset inside a row: granule16 g -> g ^ (row&7)
__device__ __forceinline__ uint32_t swz(int row, int kb, int rowbytes) {
    uint32_t g = (uint32_t)(kb >> 4);
    return (uint32_t)row * rowbytes + (((g ^ (row & 7))) << 4) + (kb & 15);
}

// =======================================================================
// Kernel A: mean over views
// =======================================================================
__global__ void mean_kernel(const float* __restrict__ pt) {
    int i = blockIdx.x * blockDim.x + threadIdx.x;
    const int total4 = KB * KM * KDIM / 4;
    if (i >= total4) return;
    const int dq = i % (KDIM / 4);
    const int bm = i / (KDIM / 4);
    const int b = bm / KM;
    const int m = bm % KM;
    const float4* base = (const float4*)pt;
    float4 s = make_float4(0.f, 0.f, 0.f, 0.f);
#pragma unroll
    for (int vw = 0; vw < KNV; vw++) {
        float4 x = base[((size_t)(b * KNV + vw) * KM + m) * (KDIM / 4) + dq];
        s.x += x.x; s.y += x.y; s.z += x.z; s.w += x.w;
    }
    const float inv = 1.0f / KNV;
    s.x *= inv; s.y *= inv; s.z *= inv; s.w *= inv;
    ((float4*)g_mean)[i] = s;
}

// =======================================================================
// Kernel P: split all weights into bf16 hi/lo swizzled operand layouts
// =======================================================================
__global__ void prep_kernel(const float* __restrict__ W1,
                            const float* __restrict__ W2) {
    int i = blockIdx.x * blockDim.x + threadIdx.x;
    if (i < 256 * 64) {
        int n = i >> 6, k = i & 63;
        float w = W1[(size_t)k * KHID + n];
        __nv_bfloat16 hi = __float2bfloat16_rn(w);
        __nv_bfloat16 lo = __float2bfloat16_rn(w - __bfloat162float(hi));
        *(__nv_bfloat16*)(g_B1 + swz(n, 2 * k, 256)) = hi;
        *(__nv_bfloat16*)(g_B1 + swz(n, 128 + 2 * k, 256)) = lo;
    } else if (i < 256 * 64 + 16 * 256) {
        int ii = i - 256 * 64;
        int o = ii >> 8, k = ii & 255;
        float w = W2[(size_t)k * KOUT + o];
        __nv_bfloat16 hi = __float2bfloat16_rn(w);
        __nv_bfloat16 lo = __float2bfloat16_rn(w - __bfloat162float(hi));
        *(__nv_bfloat16*)(g_B2 + swz(o, 2 * k, 1024)) = hi;
        *(__nv_bfloat16*)(g_B2 + swz(o, 512 + 2 * k, 1024)) = lo;
    } else if (i < 256 * 64 + 16 * 256 + 256 * 384) {
        int ii = i - (256 * 64 + 16 * 256);
        int n = ii / 384, k = ii % 384;
        float w = W1[(size_t)(KPF + k) * KHID + n];
        __nv_bfloat16 hi = __float2bfloat16_rn(w);
        __nv_bfloat16 lo = __float2bfloat16_rn(w - __bfloat162float(hi));
        int c = k >> 6, kl = k & 63;
        unsigned char* base = g_TB + (size_t)(c * 2) * 32768;
        *(__nv_bfloat16*)(base + swz(n, 2 * kl, 128)) = hi;
        *(__nv_bfloat16*)(base + 32768 + swz(n, 2 * kl, 128)) = lo;
    }
}

// =======================================================================
// Kernel B: table GEMM via bf16 3-term mma.
// grid (43, 2): block = rows m0..m0+63, n-half ny*128..+128. 256 thr.
// K=384 streamed in 6 chunks of 64 via cp.async.bulk (single buffer).
// SMEM: A [6 chunks][64r][256B hi|lo] = 96KB @0;  B chunk 32KB @98304; mbar @131072
// =======================================================================
#define TOFF_B 98304u
#define TOFF_MBAR 131072u
#define TSMEM_BYTES 131200u

__global__ void __launch_bounds__(256, 1)
table_mma_kernel(const float* __restrict__ b1) {
    extern __shared__ char smc[];
    const uint32_t sb = smem_u32(smc);
    const int t = threadIdx.x;
    const int l = t & 31;
    const int wid = t >> 5;
    const int m0 = blockIdx.x * 64;
    const int ny = blockIdx.y;

    if (t == 0) MBAR_INIT(sb + TOFF_MBAR, 1);
    __syncthreads();
    if (t == 0) {
        MBAR_EXPECT(sb + TOFF_MBAR, 32768u);
        CP_BULK(sb + TOFF_B, (const void*)(g_TB + (size_t)ny * 16384), 16384u, sb + TOFF_MBAR);
        CP_BULK(sb + TOFF_B + 16384u, (const void*)(g_TB + 32768 + (size_t)ny * 16384), 16384u, sb + TOFF_MBAR);
    }

    // ---- stage A: g_mean rows m0..m0+63, k=384 -> hi/lo per chunk ----
#pragma unroll
    for (int it = 0; it < 24; it++) {
        int idx = t + it * 256;          // 0..6143 float4s
        int r = idx / 96;
        int q = idx - r * 96;            // float4 within row (0..95)
        int col = 4 * q;
        float4 x = make_float4(0.f, 0.f, 0.f, 0.f);
        if (m0 + r < ROWS_T)
            x = *(const float4*)&g_mean[(size_t)(m0 + r) * KDIM + col];
        __nv_bfloat162 h0 = __floats2bfloat162_rn(x.x, x.y);
        __nv_bfloat162 h1 = __floats2bfloat162_rn(x.z, x.w);
        __nv_bfloat162 l0 = __floats2bfloat162_rn(x.x - __low2float(h0), x.y - __high2float(h0));
        __nv_bfloat162 l1 = __floats2bfloat162_rn(x.z - __low2float(h1), x.w - __high2float(h1));
        uint2 hp, lp;
        memcpy(&hp.x, &h0, 4); memcpy(&hp.y, &h1, 4);
        memcpy(&lp.x, &l0, 4); memcpy(&lp.y, &l1, 4);
        int c = col >> 6, kl = col & 63;
        *(uint2*)(smc + c * 16384 + swz(r, 2 * kl, 256)) = hp;
        *(uint2*)(smc + c * 16384 + swz(r, 128 + 2 * kl, 256)) = lp;
    }
    __syncthreads();

    // warp mapping: 2 m-slices x 4 n-slices of 32
    const int wm = wid & 1, wn = wid >> 1;
    const int mrow = wm * 32, ncl = wn * 32;
    const int aRow = (l & 7) + ((l >> 3) & 1) * 8;
    const int aG   = l >> 4;
    const int bRow = ((l >> 4) << 3) + (l & 7);
    const int bG   = (l >> 3) & 1;

    float acc[2][4][4];
#pragma unroll
    for (int a = 0; a < 2; a++)
#pragma unroll
        for (int b_ = 0; b_ < 4; b_++)
#pragma unroll
            for (int q = 0; q < 4; q++) acc[a][b_][q] = 0.f;

    for (int c = 0; c < 6; c++) {
        MBAR_WAIT(sb + TOFF_MBAR, c & 1);
        const uint32_t abase = sb + (uint32_t)c * 16384u;
#pragma unroll
        for (int s = 0; s < 12; s++) {
            const int ph = s >> 2, ks = s & 3;
            const int a_kb = (ph == 1 ? 128 : 0) + ks * 32;
            const uint32_t b_off = TOFF_B + (ph == 2 ? 16384u : 0u);
            const int b_kb = ks * 32;
            uint32_t af[2][4];
#pragma unroll
            for (int mt = 0; mt < 2; mt++) {
                int row = mrow + mt * 16 + aRow;
                uint32_t addr = abase + (uint32_t)row * 256u +
                                (((((a_kb >> 4) + aG)) ^ (row & 7)) << 4);
                ldsm4(addr, af[mt]);
            }
#pragma unroll
            for (int np = 0; np < 2; np++) {
                int row = ncl + np * 16 + bRow;
                uint32_t addr = sb + b_off + (uint32_t)row * 128u +
                                ((((b_kb >> 4) + bG) ^ (row & 7)) << 4);
                uint32_t bf[4];
                ldsm4(addr, bf);
#pragma unroll
                for (int mt = 0; mt < 2; mt++) {
                    mma16816(acc[mt][np * 2 + 0], af[mt], bf);
                    mma16816(acc[mt][np * 2 + 1], af[mt], bf + 2);
                }
            }
        }
        __syncthreads();
        if (c < 5 && t == 0) {
            MBAR_EXPECT(sb + TOFF_MBAR, 32768u);
            CP_BULK(sb + TOFF_B, (const void*)(g_TB + (size_t)(c + 1) * 65536 + (size_t)ny * 16384), 16384u, sb + TOFF_MBAR);
            CP_BULK(sb + TOFF_B + 16384u, (const void*)(g_TB + (size_t)(c + 1) * 65536 + 32768 + (size_t)ny * 16384), 16384u, sb + TOFF_MBAR);
        }
    }

    // ---- epilogue: + b1, store fp32 ----
    {
        const int rb = l >> 2, cq = (l & 3) * 2;
#pragma unroll
        for (int mt = 0; mt < 2; mt++) {
            int r0 = m0 + mrow + mt * 16 + rb;
            int r1 = r0 + 8;
#pragma unroll
            for (int nt = 0; nt < 4; nt++) {
                int col = ny * 128 + ncl + nt * 8 + cq;
                float2 bb = *(const float2*)&b1[col];
                if (r0 < ROWS_T)
                    *(float2*)&g_T[(size_t)r0 * KHID + col] =
                        make_float2(acc[mt][nt][0] + bb.x, acc[mt][nt][1] + bb.y);
                if (r1 < ROWS_T)
                    *(float2*)&g_T[(size_t)r1 * KHID + col] =
                        make_float2(acc[mt][nt][2] + bb.x, acc[mt][nt][3] + bb.y);
            }
        }
    }
}

// =======================================================================
// Kernel C: fused mma.sync kernel. 64 voxels / block, 256 threads (8 warps).
//   GEMM1: [64,256] splitK-concat bf16 mma (12 k-steps)
//   T-gather staged through smem (coalesced LDG -> conflict-free LDS)
//   epilogue in registers -> GEMM2 A-frags; GEMM2 per-warp k-slice + smem reduce
// SMEM: A1 16KB @0, B1 64KB @16384, B2 16KB @81920, sIdx @98304, mbar @98560
//       Ts [64][264] fl (67.6KB) reuses @0 after GEMM1; P (20KB) reuses @0 after.
// =======================================================================
#define OFF_A1   0u
#define OFF_B1   16384u
#define OFF_B2   81920u
#define OFF_SIDX 98304u
#define OFF_MBAR 98560u
#define SMEMC_BYTES 98816u
#define VB 64
#define PSTRIDE 20
#define TS_STRIDE 264

__global__ void __launch_bounds__(256, 2)
fused_kernel(const float* __restrict__ vf, const float* __restrict__ vc,
             const float* __restrict__ Km, const float* __restrict__ Rt,
             const float* __restrict__ b2, float* __restrict__ out) {
    extern __shared__ char smc[];
    const uint32_t sb = smem_u32(smc);
    const int t = threadIdx.x;
    const int l = t & 31;
    const int wid = t >> 5;
    const int g0 = blockIdx.x * VB;
    int* sIdx = (int*)(smc + OFF_SIDX);

    // ---- kick off weight bulk copies ----
    if (t == 0) {
        MBAR_INIT(sb + OFF_MBAR, 1);
        MBAR_EXPECT(sb + OFF_MBAR, 81920u);
        CP_BULK(sb + OFF_B1, (const void*)g_B1, 65536u, sb + OFF_MBAR);
        CP_BULK(sb + OFF_B2, (const void*)g_B2, 16384u, sb + OFF_MBAR);
    }

    // ---- stage A1: vf[64][64] fp32 -> bf16 hi(bytes 2k) / lo(128+2k) ----
    {
        const float4* vsrc = (const float4*)(vf + (size_t)g0 * KPF);
#pragma unroll
        for (int it = 0; it < 4; it++) {
            int idx = t + it * 256;
            int r  = idx >> 4;
            int k4 = idx & 15;
            float4 x = vsrc[idx];
            __nv_bfloat162 h0 = __floats2bfloat162_rn(x.x, x.y);
            __nv_bfloat162 h1 = __floats2bfloat162_rn(x.z, x.w);
            __nv_bfloat162 l0 = __floats2bfloat162_rn(x.x - __low2float(h0), x.y - __high2float(h0));
            __nv_bfloat162 l1 = __floats2bfloat162_rn(x.z - __low2float(h1), x.w - __high2float(h1));
            uint2 hp, lp;
            memcpy(&hp.x, &h0, 4); memcpy(&hp.y, &h1, 4);
            memcpy(&lp.x, &l0, 4); memcpy(&lp.y, &l1, 4);
            *(uint2*)(smc + OFF_A1 + swz(r, 8 * k4, 256)) = hp;
            *(uint2*)(smc + OFF_A1 + swz(r, 128 + 8 * k4, 256)) = lp;
        }
    }
    // ---- projection -> token row index ----
    if (t < VB) {
        int g = g0 + t;
        int b = g >> 16;
        const float* c = vc + (size_t)g * 3;
        float x = c[0], y = c[1], z = c[2];
        float cam0 = Rt[0] * x + Rt[1] * y + Rt[2]  * z + Rt[3];
        float cam1 = Rt[4] * x + Rt[5] * y + Rt[6]  * z + Rt[7];
        float cam2 = Rt[8] * x + Rt[9] * y + Rt[10] * z + Rt[11];
        float p0 = Km[0] * cam0 + Km[1] * cam1 + Km[2] * cam2;
        float p1 = Km[3] * cam0 + Km[4] * cam1 + Km[5] * cam2;
        float p2 = Km[6] * cam0 + Km[7] * cam1 + Km[8] * cam2;
        float denom = p2 + 1e-6f;
        float u  = __fdiv_rn(p0, denom) * (float)(518.0 / 600.0);
        float vv = __fdiv_rn(p1, denom) * (float)(518.0 / 900.0);
        int px = (int)__fdiv_rn(u, 14.0f);
        int py = (int)__fdiv_rn(vv, 14.0f);
        px = min(max(px, 0), KGRID - 1);
        py = min(max(py, 0), KGRID - 1);
        sIdx[t] = b * KM + px * KGRID + py;
    }
    __syncthreads();
    MBAR_WAIT(sb + OFF_MBAR, 0);

    // ---- GEMM1: warp tile 32m x 64n; 12 k-steps ----
    const int wm = wid & 1, wn = wid >> 1;
    const int mrow = wm * 32, ncol = wn * 64;
    const int aRow = (l & 7) + ((l >> 3) & 1) * 8;
    const int aG   = l >> 4;
    const int bRow = ((l >> 4) << 3) + (l & 7);
    const int bG   = (l >> 3) & 1;

    float acc[2][8][4];
#pragma unroll
    for (int a = 0; a < 2; a++)
#pragma unroll
        for (int b_ = 0; b_ < 8; b_++)
#pragma unroll
            for (int q = 0; q < 4; q++) acc[a][b_][q] = 0.f;

#pragma unroll
    for (int s = 0; s < 12; s++) {
        const int ph = s >> 2, ks = s & 3;
        const int a_kb = (ph == 1 ? 128 : 0) + ks * 32;
        const int b_kb = (ph == 2 ? 128 : 0) + ks * 32;
        uint32_t af[2][4];
#pragma unroll
        for (int mt = 0; mt < 2; mt++) {
            int row = mrow + mt * 16 + aRow;
            uint32_t addr = sb + OFF_A1 + (uint32_t)row * 256u +
                            (((((a_kb >> 4) + aG)) ^ (row & 7)) << 4);
            ldsm4(addr, af[mt]);
        }
#pragma unroll
        for (int np = 0; np < 4; np++) {
            int row = ncol + np * 16 + bRow;
            uint32_t addr = sb + OFF_B1 + (uint32_t)row * 256u +
                            ((((b_kb >> 4) + bG) ^ (row & 7)) << 4);
            uint32_t bf[4];
            ldsm4(addr, bf);
#pragma unroll
            for (int mt = 0; mt < 2; mt++) {
                mma16816(acc[mt][np * 2 + 0], af[mt], bf);
                mma16816(acc[mt][np * 2 + 1], af[mt], bf + 2);
            }
        }
    }
    __syncthreads();   // A1/B1 dead; region 0 becomes Ts

    // ---- stage gathered T rows into smem (coalesced) ----
    {
        float* Ts = (float*)smc;
#pragma unroll
        for (int it = 0; it < 16; it++) {
            int idx = t + it * 256;        // 0..4095
            int row = idx >> 6;            // voxel 0..63
            int q   = idx & 63;            // float4 within row
            float4 v = *(const float4*)&g_T[(size_t)sIdx[row] * KHID + 4 * q];
            *(float4*)&Ts[row * TS_STRIDE + 4 * q] = v;
        }
    }
    __syncthreads();

    // ---- epilogue in registers: +T, relu, bf16 split -> A2 frags ----
    uint32_t ah[2][4][4], al[2][4][4];
    {
        const float* Ts = (const float*)smc;
        const int rb = l >> 2, cq = (l & 3) * 2;
#pragma unroll
        for (int mt = 0; mt < 2; mt++) {
            int r0 = mrow + mt * 16 + rb;
            int r1 = r0 + 8;
#pragma unroll
            for (int nt = 0; nt < 8; nt++) {
                int c0 = ncol + nt * 8 + cq;
                float2 t0 = *(const float2*)&Ts[r0 * TS_STRIDE + c0];
                float2 t1 = *(const float2*)&Ts[r1 * TS_STRIDE + c0];
                float h00 = fmaxf(acc[mt][nt][0] + t0.x, 0.f);
                float h01 = fmaxf(acc[mt][nt][1] + t0.y, 0.f);
                float h10 = fmaxf(acc[mt][nt][2] + t1.x, 0.f);
                float h11 = fmaxf(acc[mt][nt][3] + t1.y, 0.f);
                __nv_bfloat162 hA = __floats2bfloat162_rn(h00, h01);
                __nv_bfloat162 hB = __floats2bfloat162_rn(h10, h11);
                __nv_bfloat162 lA = __floats2bfloat162_rn(h00 - __low2float(hA), h01 - __high2float(hA));
                __nv_bfloat162 lB = __floats2bfloat162_rn(h10 - __low2float(hB), h11 - __high2float(hB));
                int kb = nt >> 1, hf = (nt & 1) * 2;
                memcpy(&ah[mt][kb][hf + 0], &hA, 4);
                memcpy(&ah[mt][kb][hf + 1], &hB, 4);
                memcpy(&al[mt][kb][hf + 0], &lA, 4);
                memcpy(&al[mt][kb][hf + 1], &lB, 4);
            }
        }
    }

    // ---- GEMM2: per-warp partial over k-slice [ncol, ncol+64) ----
    float d[2][2][4];
#pragma unroll
    for (int mt = 0; mt < 2; mt++)
#pragma unroll
        for (int j = 0; j < 2; j++)
#pragma unroll
            for (int q = 0; q < 4; q++) d[mt][j][q] = 0.f;

#pragma unroll
    for (int kb = 0; kb < 4; kb++) {
        int ghi = (ncol >> 3) + 2 * kb + bG;
        int glo = 32 + (ncol >> 3) + 2 * kb + bG;
        uint32_t bhf[4], blf[4];
        uint32_t ahi_addr = sb + OFF_B2 + (uint32_t)bRow * 1024u + (((uint32_t)(ghi ^ (bRow & 7))) << 4);
        uint32_t alo_addr = sb + OFF_B2 + (uint32_t)bRow * 1024u + (((uint32_t)(glo ^ (bRow & 7))) << 4);
        ldsm4(ahi_addr, bhf);
        ldsm4(alo_addr, blf);
#pragma unroll
        for (int mt = 0; mt < 2; mt++)
#pragma unroll
            for (int j = 0; j < 2; j++) {
                mma16816(d[mt][j], ah[mt][kb], bhf + j * 2);
                mma16816(d[mt][j], al[mt][kb], bhf + j * 2);
                mma16816(d[mt][j], ah[mt][kb], blf + j * 2);
            }
    }

    __syncthreads();   // Ts dead; region 0 becomes P

    // ---- store partials P[wn][64][PSTRIDE] and reduce over wn ----
    {
        float* P = (float*)smc;
        const int rb = l >> 2, c2 = (l & 3) * 2;
#pragma unroll
        for (int mt = 0; mt < 2; mt++) {
            int r0 = mrow + mt * 16 + rb;
#pragma unroll
            for (int j = 0; j < 2; j++) {
                int cc = j * 8 + c2;
                *(float2*)&P[(wn * 64 + r0) * PSTRIDE + cc] = make_float2(d[mt][j][0], d[mt][j][1]);
                *(float2*)&P[(wn * 64 + r0 + 8) * PSTRIDE + cc] = make_float2(d[mt][j][2], d[mt][j][3]);
            }
        }
    }
    __syncthreads();
    {
        const float* P = (const float*)smc;
        int row = t >> 2;
        int cq = (t & 3) * 4;
        float4 s0 = *(const float4*)&P[(0 * 64 + row) * PSTRIDE + cq];
        float4 s1 = *(const float4*)&P[(1 * 64 + row) * PSTRIDE + cq];
        float4 s2 = *(const float4*)&P[(2 * 64 + row) * PSTRIDE + cq];
        float4 s3 = *(const float4*)&P[(3 * 64 + row) * PSTRIDE + cq];
        float4 bv = *(const float4*)(b2 + cq);
        float4 o;
        o.x = s0.x + s1.x + s2.x + s3.x + bv.x;
        o.y = s0.y + s1.y + s2.y + s3.y + bv.y;
        o.z = s0.z + s1.z + s2.z + s3.z + bv.z;
        o.w = s0.w + s1.w + s2.w + s3.w + bv.w;
        *(float4*)(out + (size_t)(g0 + row) * KOUT + cq) = o;
    }
}

// =======================================================================
extern "C" void kernel_launch(void* const* d_in, const int* in_sizes, int n_in,
                              void* d_out, int out_size) {
    (void)in_sizes; (void)n_in; (void)out_size;
    const float* pt = (const float*)d_in[0];
    const float* vf = (const float*)d_in[1];
    const float* vc = (const float*)d_in[2];
    const float* Km = (const float*)d_in[3];
    const float* Rt = (const float*)d_in[4];
    const float* W1 = (const float*)d_in[5];
    const float* b1 = (const float*)d_in[6];
    const float* W2 = (const float*)d_in[7];
    const float* b2 = (const float*)d_in[8];
    float* out = (float*)d_out;

    const int total4 = KB * KM * KDIM / 4;
    mean_kernel<<<(total4 + 255) / 256, 256>>>(pt);

    const int prep_items = 256 * 64 + 16 * 256 + 256 * 384;
    prep_kernel<<<(prep_items + 255) / 256, 256>>>(W1, W2);

    cudaFuncSetAttribute(table_mma_kernel,
                         cudaFuncAttributeMaxDynamicSharedMemorySize,
                         TSMEM_BYTES);
    dim3 gridT(ROWS_PAD / 64, 2);
    table_mma_kernel<<<gridT, 256, TSMEM_BYTES>>>(b1);

    cudaFuncSetAttribute(fused_kernel,
                         cudaFuncAttributeMaxDynamicSharedMemorySize,
                         SMEMC_BYTES);
    fused_kernel<<<KGV / VB, 256, SMEMC_BYTES>>>(vf, vc, Km, Rt, b2, out);
}

// round 7
// speedup vs baseline: 3.6031x; 1.3396x over previous
#include <cuda_runtime.h>
#include <cuda_bf16.h>
#include <cstdint>
#include <string.h>

// ---------------- problem constants ----------------
#define KB    2
#define KNV   6
#define KM    1369
#define KDIM  384
#define KV    65536
#define KPF   64
#define KHID  256
#define KOUT  16
#define KGRID 37
#define KGV   (KB*KV)
#define ROWS_T (KB*KM)        // 2738
#define ROWS_PAD 2752         // 43*64

// ---------------- device scratch ----------------
__device__ float g_mean[KB*KM*KDIM];
__device__ float g_T[KB*KM*KHID];          // token table fp32 (incl b1)
__device__ unsigned char g_B1[65536];      // W1top^T bf16 hi|lo, swizzled [256r][256B]
__device__ unsigned char g_B2[16384];      // W2^T    bf16 hi|lo, swizzled [16r][1024B]
// W1bot^T bf16, 6 chunks of k64: chunk c: hi plane [256r][128B] then lo plane
__device__ unsigned char g_TB[6*2*32768];

// ---------------- helpers ----------------
__device__ __forceinline__ uint32_t smem_u32(const void* p) {
    uint32_t a;
    asm("{ .reg .u64 t; cvta.to.shared.u64 t, %1; cvt.u32.u64 %0, t; }" : "=r"(a) : "l"(p));
    return a;
}
__device__ __forceinline__ void ldsm4(uint32_t a, uint32_t* r) {
    asm volatile("ldmatrix.sync.aligned.m8n8.x4.shared.b16 {%0,%1,%2,%3}, [%4];"
        : "=r"(r[0]), "=r"(r[1]), "=r"(r[2]), "=r"(r[3]) : "r"(a));
}
__device__ __forceinline__ void mma16816(float* c, const uint32_t* a, const uint32_t* b) {
    asm volatile("mma.sync.aligned.m16n8k16.row.col.f32.bf16.bf16.f32 "
        "{%0,%1,%2,%3}, {%4,%5,%6,%7}, {%8,%9}, {%0,%1,%2,%3};"
        : "+f"(c[0]), "+f"(c[1]), "+f"(c[2]), "+f"(c[3])
        : "r"(a[0]), "r"(a[1]), "r"(a[2]), "r"(a[3]), "r"(b[0]), "r"(b[1]));
}
#define MBAR_INIT(a, n) asm volatile("mbarrier.init.shared.b64 [%0], %1;" :: "r"(a), "r"(n) : "memory")
#define MBAR_EXPECT(a, b) asm volatile("mbarrier.arrive.expect_tx.shared.b64 _, [%0], %1;" :: "r"(a), "r"(b) : "memory")
#define MBAR_WAIT(a, ph) do { \
    uint32_t _m = (a), _p = (ph), _d; \
    asm volatile("{ .reg .pred p; mbarrier.try_wait.parity.shared.b64 p, [%1], %2; selp.b32 %0,1,0,p; }" \
        : "=r"(_d) : "r"(_m), "r"(_p) : "memory"); \
    if (!_d) { \
        asm volatile("{ .reg .pred P1;\nWL_%=:\n mbarrier.try_wait.parity.shared.b64 P1, [%0], %1;\n @P1 bra.uni WD_%=;\n bra.uni WL_%=;\nWD_%=:\n}" \
            :: "r"(_m), "r"(_p) : "memory"); \
    } } while (0)
#define CP_BULK(dst, src, bytes, mbar) \
    asm volatile("cp.async.bulk.shared::cta.global.mbarrier::complete_tx::bytes [%0], [%1], %2, [%3];" \
        :: "r"(dst), "l"(src), "r"(bytes), "r"(mbar) : "memory")

// swizzled byte offset inside a row: granule16 g -> g ^ (row&7)
__device__ __forceinline__ uint32_t swz(int row, int kb, int rowbytes) {
    uint32_t g = (uint32_t)(kb >> 4);
    return (uint32_t)row * rowbytes + (((g ^ (row & 7))) << 4) + (kb & 15);
}

// =======================================================================
// Kernel A: mean over views
// =======================================================================
__global__ void mean_kernel(const float* __restrict__ pt) {
    int i = blockIdx.x * blockDim.x + threadIdx.x;
    const int total4 = KB * KM * KDIM / 4;
    if (i >= total4) return;
    const int dq = i % (KDIM / 4);
    const int bm = i / (KDIM / 4);
    const int b = bm / KM;
    const int m = bm % KM;
    const float4* base = (const float4*)pt;
    float4 s = make_float4(0.f, 0.f, 0.f, 0.f);
#pragma unroll
    for (int vw = 0; vw < KNV; vw++) {
        float4 x = base[((size_t)(b * KNV + vw) * KM + m) * (KDIM / 4) + dq];
        s.x += x.x; s.y += x.y; s.z += x.z; s.w += x.w;
    }
    const float inv = 1.0f / KNV;
    s.x *= inv; s.y *= inv; s.z *= inv; s.w *= inv;
    ((float4*)g_mean)[i] = s;
}

// =======================================================================
// Kernel P: split all weights into bf16 hi/lo swizzled operand layouts
// =======================================================================
__global__ void prep_kernel(const float* __restrict__ W1,
                            const float* __restrict__ W2) {
    int i = blockIdx.x * blockDim.x + threadIdx.x;
    if (i < 256 * 64) {
        int n = i >> 6, k = i & 63;
        float w = W1[(size_t)k * KHID + n];
        __nv_bfloat16 hi = __float2bfloat16_rn(w);
        __nv_bfloat16 lo = __float2bfloat16_rn(w - __bfloat162float(hi));
        *(__nv_bfloat16*)(g_B1 + swz(n, 2 * k, 256)) = hi;
        *(__nv_bfloat16*)(g_B1 + swz(n, 128 + 2 * k, 256)) = lo;
    } else if (i < 256 * 64 + 16 * 256) {
        int ii = i - 256 * 64;
        int o = ii >> 8, k = ii & 255;
        float w = W2[(size_t)k * KOUT + o];
        __nv_bfloat16 hi = __float2bfloat16_rn(w);
        __nv_bfloat16 lo = __float2bfloat16_rn(w - __bfloat162float(hi));
        *(__nv_bfloat16*)(g_B2 + swz(o, 2 * k, 1024)) = hi;
        *(__nv_bfloat16*)(g_B2 + swz(o, 512 + 2 * k, 1024)) = lo;
    } else if (i < 256 * 64 + 16 * 256 + 256 * 384) {
        int ii = i - (256 * 64 + 16 * 256);
        int n = ii / 384, k = ii % 384;
        float w = W1[(size_t)(KPF + k) * KHID + n];
        __nv_bfloat16 hi = __float2bfloat16_rn(w);
        __nv_bfloat16 lo = __float2bfloat16_rn(w - __bfloat162float(hi));
        int c = k >> 6, kl = k & 63;
        unsigned char* base = g_TB + (size_t)(c * 2) * 32768;
        *(__nv_bfloat16*)(base + swz(n, 2 * kl, 128)) = hi;
        *(__nv_bfloat16*)(base + 32768 + swz(n, 2 * kl, 128)) = lo;
    }
}

// =======================================================================
// Kernel B: table GEMM via bf16 3-term mma. grid (43, 2), 256 thr.
// =======================================================================
#define TOFF_B 98304u
#define TOFF_MBAR 131072u
#define TSMEM_BYTES 131200u

__global__ void __launch_bounds__(256, 1)
table_mma_kernel(const float* __restrict__ b1) {
    extern __shared__ char smc[];
    const uint32_t sb = smem_u32(smc);
    const int t = threadIdx.x;
    const int l = t & 31;
    const int wid = t >> 5;
    const int m0 = blockIdx.x * 64;
    const int ny = blockIdx.y;

    if (t == 0) MBAR_INIT(sb + TOFF_MBAR, 1);
    __syncthreads();
    if (t == 0) {
        MBAR_EXPECT(sb + TOFF_MBAR, 32768u);
        CP_BULK(sb + TOFF_B, (const void*)(g_TB + (size_t)ny * 16384), 16384u, sb + TOFF_MBAR);
        CP_BULK(sb + TOFF_B + 16384u, (const void*)(g_TB + 32768 + (size_t)ny * 16384), 16384u, sb + TOFF_MBAR);
    }

#pragma unroll
    for (int it = 0; it < 24; it++) {
        int idx = t + it * 256;
        int r = idx / 96;
        int q = idx - r * 96;
        int col = 4 * q;
        float4 x = make_float4(0.f, 0.f, 0.f, 0.f);
        if (m0 + r < ROWS_T)
            x = *(const float4*)&g_mean[(size_t)(m0 + r) * KDIM + col];
        __nv_bfloat162 h0 = __floats2bfloat162_rn(x.x, x.y);
        __nv_bfloat162 h1 = __floats2bfloat162_rn(x.z, x.w);
        __nv_bfloat162 l0 = __floats2bfloat162_rn(x.x - __low2float(h0), x.y - __high2float(h0));
        __nv_bfloat162 l1 = __floats2bfloat162_rn(x.z - __low2float(h1), x.w - __high2float(h1));
        uint2 hp, lp;
        memcpy(&hp.x, &h0, 4); memcpy(&hp.y, &h1, 4);
        memcpy(&lp.x, &l0, 4); memcpy(&lp.y, &l1, 4);
        int c = col >> 6, kl = col & 63;
        *(uint2*)(smc + c * 16384 + swz(r, 2 * kl, 256)) = hp;
        *(uint2*)(smc + c * 16384 + swz(r, 128 + 2 * kl, 256)) = lp;
    }
    __syncthreads();

    const int wm = wid & 1, wn = wid >> 1;
    const int mrow = wm * 32, ncl = wn * 32;
    const int aRow = (l & 7) + ((l >> 3) & 1) * 8;
    const int aG   = l >> 4;
    const int bRow = ((l >> 4) << 3) + (l & 7);
    const int bG   = (l >> 3) & 1;

    float acc[2][4][4];
#pragma unroll
    for (int a = 0; a < 2; a++)
#pragma unroll
        for (int b_ = 0; b_ < 4; b_++)
#pragma unroll
            for (int q = 0; q < 4; q++) acc[a][b_][q] = 0.f;

    for (int c = 0; c < 6; c++) {
        MBAR_WAIT(sb + TOFF_MBAR, c & 1);
        const uint32_t abase = sb + (uint32_t)c * 16384u;
#pragma unroll
        for (int ks = 0; ks < 4; ks++) {
            const int kbh = ks * 32;
            uint32_t ah[2][4], al[2][4];
#pragma unroll
            for (int mt = 0; mt < 2; mt++) {
                int row = mrow + mt * 16 + aRow;
                ldsm4(abase + (uint32_t)row * 256u + ((((kbh >> 4) + aG) ^ (row & 7)) << 4), ah[mt]);
                ldsm4(abase + (uint32_t)row * 256u + (((((128 + kbh) >> 4) + aG) ^ (row & 7)) << 4), al[mt]);
            }
#pragma unroll
            for (int np = 0; np < 2; np++) {
                int row = ncl + np * 16 + bRow;
                uint32_t bh[4], bl[4];
                ldsm4(sb + TOFF_B + (uint32_t)row * 128u + ((((kbh >> 4) + bG) ^ (row & 7)) << 4), bh);
                ldsm4(sb + TOFF_B + 16384u + (uint32_t)row * 128u + ((((kbh >> 4) + bG) ^ (row & 7)) << 4), bl);
#pragma unroll
                for (int mt = 0; mt < 2; mt++) {
                    mma16816(acc[mt][np * 2 + 0], ah[mt], bh);
                    mma16816(acc[mt][np * 2 + 1], ah[mt], bh + 2);
                    mma16816(acc[mt][np * 2 + 0], al[mt], bh);
                    mma16816(acc[mt][np * 2 + 1], al[mt], bh + 2);
                    mma16816(acc[mt][np * 2 + 0], ah[mt], bl);
                    mma16816(acc[mt][np * 2 + 1], ah[mt], bl + 2);
                }
            }
        }
        __syncthreads();
        if (c < 5 && t == 0) {
            MBAR_EXPECT(sb + TOFF_MBAR, 32768u);
            CP_BULK(sb + TOFF_B, (const void*)(g_TB + (size_t)(c + 1) * 65536 + (size_t)ny * 16384), 16384u, sb + TOFF_MBAR);
            CP_BULK(sb + TOFF_B + 16384u, (const void*)(g_TB + (size_t)(c + 1) * 65536 + 32768 + (size_t)ny * 16384), 16384u, sb + TOFF_MBAR);
        }
    }

    {
        const int rb = l >> 2, cq = (l & 3) * 2;
#pragma unroll
        for (int mt = 0; mt < 2; mt++) {
            int r0 = m0 + mrow + mt * 16 + rb;
            int r1 = r0 + 8;
#pragma unroll
            for (int nt = 0; nt < 4; nt++) {
                int col = ny * 128 + ncl + nt * 8 + cq;
                float2 bb = *(const float2*)&b1[col];
                if (r0 < ROWS_T)
                    *(float2*)&g_T[(size_t)r0 * KHID + col] =
                        make_float2(acc[mt][nt][0] + bb.x, acc[mt][nt][1] + bb.y);
                if (r1 < ROWS_T)
                    *(float2*)&g_T[(size_t)r1 * KHID + col] =
                        make_float2(acc[mt][nt][2] + bb.x, acc[mt][nt][3] + bb.y);
            }
        }
    }
}

// =======================================================================
// Kernel C: fused mma.sync kernel. 64 voxels / block, 256 threads (8 warps).
//   GEMM1: fragment-shared 3-term loop (Ah/Al/Bh/Bl loaded once per k-step)
//   epilogue: direct register gather from g_T (L2), relu, bf16 split
//   GEMM2: per-warp k-slice partial + smem reduction
// =======================================================================
#define OFF_A1   0u
#define OFF_B1   16384u
#define OFF_B2   81920u
#define OFF_SIDX 98304u
#define OFF_MBAR 98560u
#define SMEMC_BYTES 98816u
#define VB 64
#define PSTRIDE 20

__global__ void __launch_bounds__(256, 2)
fused_kernel(const float* __restrict__ vf, const float* __restrict__ vc,
             const float* __restrict__ Km, const float* __restrict__ Rt,
             const float* __restrict__ b2, float* __restrict__ out) {
    extern __shared__ char smc[];
    const uint32_t sb = smem_u32(smc);
    const int t = threadIdx.x;
    const int l = t & 31;
    const int wid = t >> 5;
    const int g0 = blockIdx.x * VB;
    int* sIdx = (int*)(smc + OFF_SIDX);

    // ---- kick off weight bulk copies ----
    if (t == 0) {
        MBAR_INIT(sb + OFF_MBAR, 1);
        MBAR_EXPECT(sb + OFF_MBAR, 81920u);
        CP_BULK(sb + OFF_B1, (const void*)g_B1, 65536u, sb + OFF_MBAR);
        CP_BULK(sb + OFF_B2, (const void*)g_B2, 16384u, sb + OFF_MBAR);
    }

    // ---- stage A1: vf[64][64] fp32 -> bf16 hi(bytes 2k) / lo(128+2k) ----
    {
        const float4* vsrc = (const float4*)(vf + (size_t)g0 * KPF);
#pragma unroll
        for (int it = 0; it < 4; it++) {
            int idx = t + it * 256;
            int r  = idx >> 4;
            int k4 = idx & 15;
            float4 x = vsrc[idx];
            __nv_bfloat162 h0 = __floats2bfloat162_rn(x.x, x.y);
            __nv_bfloat162 h1 = __floats2bfloat162_rn(x.z, x.w);
            __nv_bfloat162 l0 = __floats2bfloat162_rn(x.x - __low2float(h0), x.y - __high2float(h0));
            __nv_bfloat162 l1 = __floats2bfloat162_rn(x.z - __low2float(h1), x.w - __high2float(h1));
            uint2 hp, lp;
            memcpy(&hp.x, &h0, 4); memcpy(&hp.y, &h1, 4);
            memcpy(&lp.x, &l0, 4); memcpy(&lp.y, &l1, 4);
            *(uint2*)(smc + OFF_A1 + swz(r, 8 * k4, 256)) = hp;
            *(uint2*)(smc + OFF_A1 + swz(r, 128 + 8 * k4, 256)) = lp;
        }
    }
    // ---- projection -> token row index ----
    if (t < VB) {
        int g = g0 + t;
        int b = g >> 16;
        const float* c = vc + (size_t)g * 3;
        float x = c[0], y = c[1], z = c[2];
        float cam0 = Rt[0] * x + Rt[1] * y + Rt[2]  * z + Rt[3];
        float cam1 = Rt[4] * x + Rt[5] * y + Rt[6]  * z + Rt[7];
        float cam2 = Rt[8] * x + Rt[9] * y + Rt[10] * z + Rt[11];
        float p0 = Km[0] * cam0 + Km[1] * cam1 + Km[2] * cam2;
        float p1 = Km[3] * cam0 + Km[4] * cam1 + Km[5] * cam2;
        float p2 = Km[6] * cam0 + Km[7] * cam1 + Km[8] * cam2;
        float denom = p2 + 1e-6f;
        float u  = __fdiv_rn(p0, denom) * (float)(518.0 / 600.0);
        float vv = __fdiv_rn(p1, denom) * (float)(518.0 / 900.0);
        int px = (int)__fdiv_rn(u, 14.0f);
        int py = (int)__fdiv_rn(vv, 14.0f);
        px = min(max(px, 0), KGRID - 1);
        py = min(max(py, 0), KGRID - 1);
        sIdx[t] = b * KM + px * KGRID + py;
    }
    __syncthreads();
    MBAR_WAIT(sb + OFF_MBAR, 0);

    // ---- GEMM1: warp tile 32m x 64n; 4 k-steps, fragments shared ----
    const int wm = wid & 1, wn = wid >> 1;
    const int mrow = wm * 32, ncol = wn * 64;
    const int aRow = (l & 7) + ((l >> 3) & 1) * 8;
    const int aG   = l >> 4;
    const int bRow = ((l >> 4) << 3) + (l & 7);
    const int bG   = (l >> 3) & 1;

    float acc[2][8][4];
#pragma unroll
    for (int a = 0; a < 2; a++)
#pragma unroll
        for (int b_ = 0; b_ < 8; b_++)
#pragma unroll
            for (int q = 0; q < 4; q++) acc[a][b_][q] = 0.f;

#pragma unroll
    for (int ks = 0; ks < 4; ks++) {
        const int kb = ks * 32;
        uint32_t ahf[2][4], alf[2][4];
#pragma unroll
        for (int mt = 0; mt < 2; mt++) {
            int row = mrow + mt * 16 + aRow;
            uint32_t rbase = sb + OFF_A1 + (uint32_t)row * 256u;
            ldsm4(rbase + ((((kb >> 4) + aG) ^ (row & 7)) << 4), ahf[mt]);
            ldsm4(rbase + (((((128 + kb) >> 4) + aG) ^ (row & 7)) << 4), alf[mt]);
        }
#pragma unroll
        for (int np = 0; np < 4; np++) {
            int row = ncol + np * 16 + bRow;
            uint32_t rbase = sb + OFF_B1 + (uint32_t)row * 256u;
            uint32_t bh[4], bl[4];
            ldsm4(rbase + ((((kb >> 4) + bG) ^ (row & 7)) << 4), bh);
            ldsm4(rbase + (((((128 + kb) >> 4) + bG) ^ (row & 7)) << 4), bl);
#pragma unroll
            for (int mt = 0; mt < 2; mt++) {
                mma16816(acc[mt][np * 2 + 0], ahf[mt], bh);
                mma16816(acc[mt][np * 2 + 1], ahf[mt], bh + 2);
                mma16816(acc[mt][np * 2 + 0], alf[mt], bh);
                mma16816(acc[mt][np * 2 + 1], alf[mt], bh + 2);
                mma16816(acc[mt][np * 2 + 0], ahf[mt], bl);
                mma16816(acc[mt][np * 2 + 1], ahf[mt], bl + 2);
            }
        }
    }

    // ---- epilogue IN REGISTERS: +gather(g_T), relu, bf16 split -> A2 frags ----
    uint32_t ah[2][4][4], al[2][4][4];
    {
        const int rb = l >> 2, cq = (l & 3) * 2;
#pragma unroll
        for (int mt = 0; mt < 2; mt++) {
            int r0 = mrow + mt * 16 + rb;
            int r1 = r0 + 8;
            const float* T0 = g_T + (size_t)sIdx[r0] * KHID;
            const float* T1 = g_T + (size_t)sIdx[r1] * KHID;
#pragma unroll
            for (int nt = 0; nt < 8; nt++) {
                int c0 = ncol + nt * 8 + cq;
                float2 t0 = *(const float2*)(T0 + c0);
                float2 t1 = *(const float2*)(T1 + c0);
                float h00 = fmaxf(acc[mt][nt][0] + t0.x, 0.f);
                float h01 = fmaxf(acc[mt][nt][1] + t0.y, 0.f);
                float h10 = fmaxf(acc[mt][nt][2] + t1.x, 0.f);
                float h11 = fmaxf(acc[mt][nt][3] + t1.y, 0.f);
                __nv_bfloat162 hA = __floats2bfloat162_rn(h00, h01);
                __nv_bfloat162 hB = __floats2bfloat162_rn(h10, h11);
                __nv_bfloat162 lA = __floats2bfloat162_rn(h00 - __low2float(hA), h01 - __high2float(hA));
                __nv_bfloat162 lB = __floats2bfloat162_rn(h10 - __low2float(hB), h11 - __high2float(hB));
                int kb = nt >> 1, hf = (nt & 1) * 2;
                memcpy(&ah[mt][kb][hf + 0], &hA, 4);
                memcpy(&ah[mt][kb][hf + 1], &hB, 4);
                memcpy(&al[mt][kb][hf + 0], &lA, 4);
                memcpy(&al[mt][kb][hf + 1], &lB, 4);
            }
        }
    }

    // ---- GEMM2: per-warp partial over k-slice [ncol, ncol+64) ----
    float d[2][2][4];
#pragma unroll
    for (int mt = 0; mt < 2; mt++)
#pragma unroll
        for (int j = 0; j < 2; j++)
#pragma unroll
            for (int q = 0; q < 4; q++) d[mt][j][q] = 0.f;

#pragma unroll
    for (int kb = 0; kb < 4; kb++) {
        int ghi = (ncol >> 3) + 2 * kb + bG;
        int glo = 32 + (ncol >> 3) + 2 * kb + bG;
        uint32_t bhf[4], blf[4];
        ldsm4(sb + OFF_B2 + (uint32_t)bRow * 1024u + (((uint32_t)(ghi ^ (bRow & 7))) << 4), bhf);
        ldsm4(sb + OFF_B2 + (uint32_t)bRow * 1024u + (((uint32_t)(glo ^ (bRow & 7))) << 4), blf);
#pragma unroll
        for (int mt = 0; mt < 2; mt++)
#pragma unroll
            for (int j = 0; j < 2; j++) {
                mma16816(d[mt][j], ah[mt][kb], bhf + j * 2);
                mma16816(d[mt][j], al[mt][kb], bhf + j * 2);
                mma16816(d[mt][j], ah[mt][kb], blf + j * 2);
            }
    }

    __syncthreads();   // A1/B1 region dead -> reuse as P

    // ---- store partials P[wn][64][PSTRIDE] and reduce over wn ----
    {
        float* P = (float*)smc;
        const int rb = l >> 2, c2 = (l & 3) * 2;
#pragma unroll
        for (int mt = 0; mt < 2; mt++) {
            int r0 = mrow + mt * 16 + rb;
#pragma unroll
            for (int j = 0; j < 2; j++) {
                int cc = j * 8 + c2;
                *(float2*)&P[(wn * 64 + r0) * PSTRIDE + cc] = make_float2(d[mt][j][0], d[mt][j][1]);
                *(float2*)&P[(wn * 64 + r0 + 8) * PSTRIDE + cc] = make_float2(d[mt][j][2], d[mt][j][3]);
            }
        }
    }
    __syncthreads();
    {
        const float* P = (const float*)smc;
        int row = t >> 2;
        int cq = (t & 3) * 4;
        float4 s0 = *(const float4*)&P[(0 * 64 + row) * PSTRIDE + cq];
        float4 s1 = *(const float4*)&P[(1 * 64 + row) * PSTRIDE + cq];
        float4 s2 = *(const float4*)&P[(2 * 64 + row) * PSTRIDE + cq];
        float4 s3 = *(const float4*)&P[(3 * 64 + row) * PSTRIDE + cq];
        float4 bv = *(const float4*)(b2 + cq);
        float4 o;
        o.x = s0.x + s1.x + s2.x + s3.x + bv.x;
        o.y = s0.y + s1.y + s2.y + s3.y + bv.y;
        o.z = s0.z + s1.z + s2.z + s3.z + bv.z;
        o.w = s0.w + s1.w + s2.w + s3.w + bv.w;
        *(float4*)(out + (size_t)(g0 + row) * KOUT + cq) = o;
    }
}

// =======================================================================
extern "C" void kernel_launch(void* const* d_in, const int* in_sizes, int n_in,
                              void* d_out, int out_size) {
    (void)in_sizes; (void)n_in; (void)out_size;
    const float* pt = (const float*)d_in[0];
    const float* vf = (const float*)d_in[1];
    const float* vc = (const float*)d_in[2];
    const float* Km = (const float*)d_in[3];
    const float* Rt = (const float*)d_in[4];
    const float* W1 = (const float*)d_in[5];
    const float* b1 = (const float*)d_in[6];
    const float* W2 = (const float*)d_in[7];
    const float* b2 = (const float*)d_in[8];
    float* out = (float*)d_out;

    const int total4 = KB * KM * KDIM / 4;
    mean_kernel<<<(total4 + 255) / 256, 256>>>(pt);

    const int prep_items = 256 * 64 + 16 * 256 + 256 * 384;
    prep_kernel<<<(prep_items + 255) / 256, 256>>>(W1, W2);

    cudaFuncSetAttribute(table_mma_kernel,
                         cudaFuncAttributeMaxDynamicSharedMemorySize,
                         TSMEM_BYTES);
    dim3 gridT(ROWS_PAD / 64, 2);
    table_mma_kernel<<<gridT, 256, TSMEM_BYTES>>>(b1);

    cudaFuncSetAttribute(fused_kernel,
                         cudaFuncAttributeMaxDynamicSharedMemorySize,
                         SMEMC_BYTES);
    fused_kernel<<<KGV / VB, 256, SMEMC_BYTES>>>(vf, vc, Km, Rt, b2, out);
}

// round 8
// speedup vs baseline: 4.1319x; 1.1468x over previous
#include <cuda_runtime.h>
#include <cuda_bf16.h>
#include <cuda_fp16.h>
#include <cstdint>
#include <string.h>

// ---------------- problem constants ----------------
#define KB    2
#define KNV   6
#define KM    1369
#define KDIM  384
#define KV    65536
#define KPF   64
#define KHID  256
#define KOUT  16
#define KGRID 37
#define KGV   (KB*KV)
#define ROWS_T (KB*KM)        // 2738
#define ROWS_PAD 2752         // 43*64

// ---------------- device scratch ----------------
__device__ float g_mean[KB*KM*KDIM];
__device__ float g_T[KB*KM*KHID];          // token table fp32 (incl b1)
__device__ unsigned char g_B1[32768];      // W1top^T fp16 hi, swizzled [256r][128B]
__device__ unsigned char g_B2[8192];       // W2^T    fp16 hi, swizzled [16r][512B]
// W1bot^T bf16 (3-term table path), 6 chunks of k64: hi plane then lo plane
__device__ unsigned char g_TB[6*2*32768];

// ---------------- helpers ----------------
__device__ __forceinline__ uint32_t smem_u32(const void* p) {
    uint32_t a;
    asm("{ .reg .u64 t; cvta.to.shared.u64 t, %1; cvt.u32.u64 %0, t; }" : "=r"(a) : "l"(p));
    return a;
}
__device__ __forceinline__ void ldsm4(uint32_t a, uint32_t* r) {
    asm volatile("ldmatrix.sync.aligned.m8n8.x4.shared.b16 {%0,%1,%2,%3}, [%4];"
        : "=r"(r[0]), "=r"(r[1]), "=r"(r[2]), "=r"(r[3]) : "r"(a));
}
// bf16 mma (table kernel)
__device__ __forceinline__ void mma16816(float* c, const uint32_t* a, const uint32_t* b) {
    asm volatile("mma.sync.aligned.m16n8k16.row.col.f32.bf16.bf16.f32 "
        "{%0,%1,%2,%3}, {%4,%5,%6,%7}, {%8,%9}, {%0,%1,%2,%3};"
        : "+f"(c[0]), "+f"(c[1]), "+f"(c[2]), "+f"(c[3])
        : "r"(a[0]), "r"(a[1]), "r"(a[2]), "r"(a[3]), "r"(b[0]), "r"(b[1]));
}
// fp16 mma (fused kernel)
__device__ __forceinline__ void mma16816h(float* c, const uint32_t* a, const uint32_t* b) {
    asm volatile("mma.sync.aligned.m16n8k16.row.col.f32.f16.f16.f32 "
        "{%0,%1,%2,%3}, {%4,%5,%6,%7}, {%8,%9}, {%0,%1,%2,%3};"
        : "+f"(c[0]), "+f"(c[1]), "+f"(c[2]), "+f"(c[3])
        : "r"(a[0]), "r"(a[1]), "r"(a[2]), "r"(a[3]), "r"(b[0]), "r"(b[1]));
}
#define MBAR_INIT(a, n) asm volatile("mbarrier.init.shared.b64 [%0], %1;" :: "r"(a), "r"(n) : "memory")
#define MBAR_EXPECT(a, b) asm volatile("mbarrier.arrive.expect_tx.shared.b64 _, [%0], %1;" :: "r"(a), "r"(b) : "memory")
#define MBAR_WAIT(a, ph) do { \
    uint32_t _m = (a), _p = (ph), _d; \
    asm volatile("{ .reg .pred p; mbarrier.try_wait.parity.shared.b64 p, [%1], %2; selp.b32 %0,1,0,p; }" \
        : "=r"(_d) : "r"(_m), "r"(_p) : "memory"); \
    if (!_d) { \
        asm volatile("{ .reg .pred P1;\nWL_%=:\n mbarrier.try_wait.parity.shared.b64 P1, [%0], %1;\n @P1 bra.uni WD_%=;\n bra.uni WL_%=;\nWD_%=:\n}" \
            :: "r"(_m), "r"(_p) : "memory"); \
    } } while (0)
#define CP_BULK(dst, src, bytes, mbar) \
    asm volatile("cp.async.bulk.shared::cta.global.mbarrier::complete_tx::bytes [%0], [%1], %2, [%3];" \
        :: "r"(dst), "l"(src), "r"(bytes), "r"(mbar) : "memory")

// swizzled byte offset inside a row: granule16 g -> g ^ (row&7)
__device__ __forceinline__ uint32_t swz(int row, int kb, int rowbytes) {
    uint32_t g = (uint32_t)(kb >> 4);
    return (uint32_t)row * rowbytes + (((g ^ (row & 7))) << 4) + (kb & 15);
}

// =======================================================================
// Kernel A: mean over views
// =======================================================================
__global__ void mean_kernel(const float* __restrict__ pt) {
    int i = blockIdx.x * blockDim.x + threadIdx.x;
    const int total4 = KB * KM * KDIM / 4;
    if (i >= total4) return;
    const int dq = i % (KDIM / 4);
    const int bm = i / (KDIM / 4);
    const int b = bm / KM;
    const int m = bm % KM;
    const float4* base = (const float4*)pt;
    float4 s = make_float4(0.f, 0.f, 0.f, 0.f);
#pragma unroll
    for (int vw = 0; vw < KNV; vw++) {
        float4 x = base[((size_t)(b * KNV + vw) * KM + m) * (KDIM / 4) + dq];
        s.x += x.x; s.y += x.y; s.z += x.z; s.w += x.w;
    }
    const float inv = 1.0f / KNV;
    s.x *= inv; s.y *= inv; s.z *= inv; s.w *= inv;
    ((float4*)g_mean)[i] = s;
}

// =======================================================================
// Kernel P: weight prep.
//   g_B1: W1top^T fp16 (hi only), rows n<256, rowbytes 128 (k<64)
//   g_B2: W2^T    fp16 (hi only), rows o<16,  rowbytes 512 (k<256)
//   g_TB: W1bot^T bf16 hi/lo (table path, 3-term)
// =======================================================================
__global__ void prep_kernel(const float* __restrict__ W1,
                            const float* __restrict__ W2) {
    int i = blockIdx.x * blockDim.x + threadIdx.x;
    if (i < 256 * 64) {
        int n = i >> 6, k = i & 63;
        float w = W1[(size_t)k * KHID + n];
        *(__half*)(g_B1 + swz(n, 2 * k, 128)) = __float2half_rn(w);
    } else if (i < 256 * 64 + 16 * 256) {
        int ii = i - 256 * 64;
        int o = ii >> 8, k = ii & 255;
        float w = W2[(size_t)k * KOUT + o];
        *(__half*)(g_B2 + swz(o, 2 * k, 512)) = __float2half_rn(w);
    } else if (i < 256 * 64 + 16 * 256 + 256 * 384) {
        int ii = i - (256 * 64 + 16 * 256);
        int n = ii / 384, k = ii % 384;
        float w = W1[(size_t)(KPF + k) * KHID + n];
        __nv_bfloat16 hi = __float2bfloat16_rn(w);
        __nv_bfloat16 lo = __float2bfloat16_rn(w - __bfloat162float(hi));
        int c = k >> 6, kl = k & 63;
        unsigned char* base = g_TB + (size_t)(c * 2) * 32768;
        *(__nv_bfloat16*)(base + swz(n, 2 * kl, 128)) = hi;
        *(__nv_bfloat16*)(base + 32768 + swz(n, 2 * kl, 128)) = lo;
    }
}

// =======================================================================
// Kernel B: table GEMM via bf16 3-term mma. grid (43, 2), 256 thr.
// =======================================================================
#define TOFF_B 98304u
#define TOFF_MBAR 131072u
#define TSMEM_BYTES 131200u

__global__ void __launch_bounds__(256, 1)
table_mma_kernel(const float* __restrict__ b1) {
    extern __shared__ char smc[];
    const uint32_t sb = smem_u32(smc);
    const int t = threadIdx.x;
    const int l = t & 31;
    const int wid = t >> 5;
    const int m0 = blockIdx.x * 64;
    const int ny = blockIdx.y;

    if (t == 0) MBAR_INIT(sb + TOFF_MBAR, 1);
    __syncthreads();
    if (t == 0) {
        MBAR_EXPECT(sb + TOFF_MBAR, 32768u);
        CP_BULK(sb + TOFF_B, (const void*)(g_TB + (size_t)ny * 16384), 16384u, sb + TOFF_MBAR);
        CP_BULK(sb + TOFF_B + 16384u, (const void*)(g_TB + 32768 + (size_t)ny * 16384), 16384u, sb + TOFF_MBAR);
    }

#pragma unroll
    for (int it = 0; it < 24; it++) {
        int idx = t + it * 256;
        int r = idx / 96;
        int q = idx - r * 96;
        int col = 4 * q;
        float4 x = make_float4(0.f, 0.f, 0.f, 0.f);
        if (m0 + r < ROWS_T)
            x = *(const float4*)&g_mean[(size_t)(m0 + r) * KDIM + col];
        __nv_bfloat162 h0 = __floats2bfloat162_rn(x.x, x.y);
        __nv_bfloat162 h1 = __floats2bfloat162_rn(x.z, x.w);
        __nv_bfloat162 l0 = __floats2bfloat162_rn(x.x - __low2float(h0), x.y - __high2float(h0));
        __nv_bfloat162 l1 = __floats2bfloat162_rn(x.z - __low2float(h1), x.w - __high2float(h1));
        uint2 hp, lp;
        memcpy(&hp.x, &h0, 4); memcpy(&hp.y, &h1, 4);
        memcpy(&lp.x, &l0, 4); memcpy(&lp.y, &l1, 4);
        int c = col >> 6, kl = col & 63;
        *(uint2*)(smc + c * 16384 + swz(r, 2 * kl, 256)) = hp;
        *(uint2*)(smc + c * 16384 + swz(r, 128 + 2 * kl, 256)) = lp;
    }
    __syncthreads();

    const int wm = wid & 1, wn = wid >> 1;
    const int mrow = wm * 32, ncl = wn * 32;
    const int aRow = (l & 7) + ((l >> 3) & 1) * 8;
    const int aG   = l >> 4;
    const int bRow = ((l >> 4) << 3) + (l & 7);
    const int bG   = (l >> 3) & 1;

    float acc[2][4][4];
#pragma unroll
    for (int a = 0; a < 2; a++)
#pragma unroll
        for (int b_ = 0; b_ < 4; b_++)
#pragma unroll
            for (int q = 0; q < 4; q++) acc[a][b_][q] = 0.f;

    for (int c = 0; c < 6; c++) {
        MBAR_WAIT(sb + TOFF_MBAR, c & 1);
        const uint32_t abase = sb + (uint32_t)c * 16384u;
#pragma unroll
        for (int ks = 0; ks < 4; ks++) {
            const int kbh = ks * 32;
            uint32_t ah[2][4], al[2][4];
#pragma unroll
            for (int mt = 0; mt < 2; mt++) {
                int row = mrow + mt * 16 + aRow;
                ldsm4(abase + (uint32_t)row * 256u + ((((kbh >> 4) + aG) ^ (row & 7)) << 4), ah[mt]);
                ldsm4(abase + (uint32_t)row * 256u + (((((128 + kbh) >> 4) + aG) ^ (row & 7)) << 4), al[mt]);
            }
#pragma unroll
            for (int np = 0; np < 2; np++) {
                int row = ncl + np * 16 + bRow;
                uint32_t bh[4], bl[4];
                ldsm4(sb + TOFF_B + (uint32_t)row * 128u + ((((kbh >> 4) + bG) ^ (row & 7)) << 4), bh);
                ldsm4(sb + TOFF_B + 16384u + (uint32_t)row * 128u + ((((kbh >> 4) + bG) ^ (row & 7)) << 4), bl);
#pragma unroll
                for (int mt = 0; mt < 2; mt++) {
                    mma16816(acc[mt][np * 2 + 0], ah[mt], bh);
                    mma16816(acc[mt][np * 2 + 1], ah[mt], bh + 2);
                    mma16816(acc[mt][np * 2 + 0], al[mt], bh);
                    mma16816(acc[mt][np * 2 + 1], al[mt], bh + 2);
                    mma16816(acc[mt][np * 2 + 0], ah[mt], bl);
                    mma16816(acc[mt][np * 2 + 1], ah[mt], bl + 2);
                }
            }
        }
        __syncthreads();
        if (c < 5 && t == 0) {
            MBAR_EXPECT(sb + TOFF_MBAR, 32768u);
            CP_BULK(sb + TOFF_B, (const void*)(g_TB + (size_t)(c + 1) * 65536 + (size_t)ny * 16384), 16384u, sb + TOFF_MBAR);
            CP_BULK(sb + TOFF_B + 16384u, (const void*)(g_TB + (size_t)(c + 1) * 65536 + 32768 + (size_t)ny * 16384), 16384u, sb + TOFF_MBAR);
        }
    }

    {
        const int rb = l >> 2, cq = (l & 3) * 2;
#pragma unroll
        for (int mt = 0; mt < 2; mt++) {
            int r0 = m0 + mrow + mt * 16 + rb;
            int r1 = r0 + 8;
#pragma unroll
            for (int nt = 0; nt < 4; nt++) {
                int col = ny * 128 + ncl + nt * 8 + cq;
                float2 bb = *(const float2*)&b1[col];
                if (r0 < ROWS_T)
                    *(float2*)&g_T[(size_t)r0 * KHID + col] =
                        make_float2(acc[mt][nt][0] + bb.x, acc[mt][nt][1] + bb.y);
                if (r1 < ROWS_T)
                    *(float2*)&g_T[(size_t)r1 * KHID + col] =
                        make_float2(acc[mt][nt][2] + bb.x, acc[mt][nt][3] + bb.y);
            }
        }
    }
}

// =======================================================================
// Kernel C: fused fp16 2-term mma kernel. 64 voxels / block, 8 warps.
//   GEMM1: (Ah+Al) @ B1h  — 2 MMAs per logical k16
//   epilogue: +gather(g_T), relu, fp16 hi/lo split in registers
//   GEMM2: (Hh+Hl) @ B2h per-warp k-slice + smem reduction
// SMEM: A1 16KB @0, B1 32KB @16384, B2 8KB @49152, sIdx @57344, mbar @57600
// =======================================================================
#define OFF_A1   0u
#define OFF_B1   16384u
#define OFF_B2   49152u
#define OFF_SIDX 57344u
#define OFF_MBAR 57600u
#define SMEMC_BYTES 57728u
#define VB 64
#define PSTRIDE 20

__global__ void __launch_bounds__(256, 2)
fused_kernel(const float* __restrict__ vf, const float* __restrict__ vc,
             const float* __restrict__ Km, const float* __restrict__ Rt,
             const float* __restrict__ b2, float* __restrict__ out) {
    extern __shared__ char smc[];
    const uint32_t sb = smem_u32(smc);
    const int t = threadIdx.x;
    const int l = t & 31;
    const int wid = t >> 5;
    const int g0 = blockIdx.x * VB;
    int* sIdx = (int*)(smc + OFF_SIDX);

    // ---- kick off weight bulk copies ----
    if (t == 0) {
        MBAR_INIT(sb + OFF_MBAR, 1);
        MBAR_EXPECT(sb + OFF_MBAR, 40960u);
        CP_BULK(sb + OFF_B1, (const void*)g_B1, 32768u, sb + OFF_MBAR);
        CP_BULK(sb + OFF_B2, (const void*)g_B2, 8192u, sb + OFF_MBAR);
    }

    // ---- stage A1: vf[64][64] fp32 -> fp16 hi(bytes 2k) / lo(128+2k) ----
    {
        const float4* vsrc = (const float4*)(vf + (size_t)g0 * KPF);
#pragma unroll
        for (int it = 0; it < 4; it++) {
            int idx = t + it * 256;
            int r  = idx >> 4;
            int k4 = idx & 15;
            float4 x = vsrc[idx];
            __half2 h0 = __float22half2_rn(make_float2(x.x, x.y));
            __half2 h1 = __float22half2_rn(make_float2(x.z, x.w));
            float2 h0f = __half22float2(h0);
            float2 h1f = __half22float2(h1);
            __half2 l0 = __float22half2_rn(make_float2(x.x - h0f.x, x.y - h0f.y));
            __half2 l1 = __float22half2_rn(make_float2(x.z - h1f.x, x.w - h1f.y));
            uint2 hp, lp;
            memcpy(&hp.x, &h0, 4); memcpy(&hp.y, &h1, 4);
            memcpy(&lp.x, &l0, 4); memcpy(&lp.y, &l1, 4);
            *(uint2*)(smc + OFF_A1 + swz(r, 8 * k4, 256)) = hp;
            *(uint2*)(smc + OFF_A1 + swz(r, 128 + 8 * k4, 256)) = lp;
        }
    }
    // ---- projection -> token row index ----
    if (t < VB) {
        int g = g0 + t;
        int b = g >> 16;
        const float* c = vc + (size_t)g * 3;
        float x = c[0], y = c[1], z = c[2];
        float cam0 = Rt[0] * x + Rt[1] * y + Rt[2]  * z + Rt[3];
        float cam1 = Rt[4] * x + Rt[5] * y + Rt[6]  * z + Rt[7];
        float cam2 = Rt[8] * x + Rt[9] * y + Rt[10] * z + Rt[11];
        float p0 = Km[0] * cam0 + Km[1] * cam1 + Km[2] * cam2;
        float p1 = Km[3] * cam0 + Km[4] * cam1 + Km[5] * cam2;
        float p2 = Km[6] * cam0 + Km[7] * cam1 + Km[8] * cam2;
        float denom = p2 + 1e-6f;
        float u  = __fdiv_rn(p0, denom) * (float)(518.0 / 600.0);
        float vv = __fdiv_rn(p1, denom) * (float)(518.0 / 900.0);
        int px = (int)__fdiv_rn(u, 14.0f);
        int py = (int)__fdiv_rn(vv, 14.0f);
        px = min(max(px, 0), KGRID - 1);
        py = min(max(py, 0), KGRID - 1);
        sIdx[t] = b * KM + px * KGRID + py;
    }
    __syncthreads();
    MBAR_WAIT(sb + OFF_MBAR, 0);

    // ---- GEMM1: warp tile 32m x 64n; 4 k-steps, 2-term fp16 ----
    const int wm = wid & 1, wn = wid >> 1;
    const int mrow = wm * 32, ncol = wn * 64;
    const int aRow = (l & 7) + ((l >> 3) & 1) * 8;
    const int aG   = l >> 4;
    const int bRow = ((l >> 4) << 3) + (l & 7);
    const int bG   = (l >> 3) & 1;

    float acc[2][8][4];
#pragma unroll
    for (int a = 0; a < 2; a++)
#pragma unroll
        for (int b_ = 0; b_ < 8; b_++)
#pragma unroll
            for (int q = 0; q < 4; q++) acc[a][b_][q] = 0.f;

#pragma unroll
    for (int ks = 0; ks < 4; ks++) {
        const int kb = ks * 32;
        uint32_t ahf[2][4], alf[2][4];
#pragma unroll
        for (int mt = 0; mt < 2; mt++) {
            int row = mrow + mt * 16 + aRow;
            uint32_t rbase = sb + OFF_A1 + (uint32_t)row * 256u;
            ldsm4(rbase + ((((kb >> 4) + aG) ^ (row & 7)) << 4), ahf[mt]);
            ldsm4(rbase + (((((128 + kb) >> 4) + aG) ^ (row & 7)) << 4), alf[mt]);
        }
#pragma unroll
        for (int np = 0; np < 4; np++) {
            int row = ncol + np * 16 + bRow;
            uint32_t bh[4];
            ldsm4(sb + OFF_B1 + (uint32_t)row * 128u + ((((kb >> 4) + bG) ^ (row & 7)) << 4), bh);
#pragma unroll
            for (int mt = 0; mt < 2; mt++) {
                mma16816h(acc[mt][np * 2 + 0], ahf[mt], bh);
                mma16816h(acc[mt][np * 2 + 1], ahf[mt], bh + 2);
                mma16816h(acc[mt][np * 2 + 0], alf[mt], bh);
                mma16816h(acc[mt][np * 2 + 1], alf[mt], bh + 2);
            }
        }
    }

    // ---- epilogue IN REGISTERS: +gather(g_T), relu, fp16 split ----
    uint32_t ah[2][4][4], al[2][4][4];
    {
        const int rb = l >> 2, cq = (l & 3) * 2;
#pragma unroll
        for (int mt = 0; mt < 2; mt++) {
            int r0 = mrow + mt * 16 + rb;
            int r1 = r0 + 8;
            const float* T0 = g_T + (size_t)sIdx[r0] * KHID;
            const float* T1 = g_T + (size_t)sIdx[r1] * KHID;
#pragma unroll
            for (int nt = 0; nt < 8; nt++) {
                int c0 = ncol + nt * 8 + cq;
                float2 t0 = *(const float2*)(T0 + c0);
                float2 t1 = *(const float2*)(T1 + c0);
                float h00 = fmaxf(acc[mt][nt][0] + t0.x, 0.f);
                float h01 = fmaxf(acc[mt][nt][1] + t0.y, 0.f);
                float h10 = fmaxf(acc[mt][nt][2] + t1.x, 0.f);
                float h11 = fmaxf(acc[mt][nt][3] + t1.y, 0.f);
                __half2 hA = __float22half2_rn(make_float2(h00, h01));
                __half2 hB = __float22half2_rn(make_float2(h10, h11));
                float2 hAf = __half22float2(hA);
                float2 hBf = __half22float2(hB);
                __half2 lA = __float22half2_rn(make_float2(h00 - hAf.x, h01 - hAf.y));
                __half2 lB = __float22half2_rn(make_float2(h10 - hBf.x, h11 - hBf.y));
                int kb = nt >> 1, hf = (nt & 1) * 2;
                memcpy(&ah[mt][kb][hf + 0], &hA, 4);
                memcpy(&ah[mt][kb][hf + 1], &hB, 4);
                memcpy(&al[mt][kb][hf + 0], &lA, 4);
                memcpy(&al[mt][kb][hf + 1], &lB, 4);
            }
        }
    }

    // ---- GEMM2: per-warp partial over k-slice [ncol, ncol+64), 2-term ----
    float d[2][2][4];
#pragma unroll
    for (int mt = 0; mt < 2; mt++)
#pragma unroll
        for (int j = 0; j < 2; j++)
#pragma unroll
            for (int q = 0; q < 4; q++) d[mt][j][q] = 0.f;

#pragma unroll
    for (int kb = 0; kb < 4; kb++) {
        int ghi = (ncol >> 3) + 2 * kb + bG;
        uint32_t bhf[4];
        ldsm4(sb + OFF_B2 + (uint32_t)bRow * 512u + (((uint32_t)(ghi ^ (bRow & 7))) << 4), bhf);
#pragma unroll
        for (int mt = 0; mt < 2; mt++)
#pragma unroll
            for (int j = 0; j < 2; j++) {
                mma16816h(d[mt][j], ah[mt][kb], bhf + j * 2);
                mma16816h(d[mt][j], al[mt][kb], bhf + j * 2);
            }
    }

    __syncthreads();   // A1/B1 region dead -> reuse as P

    // ---- store partials P[wn][64][PSTRIDE] and reduce over wn ----
    {
        float* P = (float*)smc;
        const int rb = l >> 2, c2 = (l & 3) * 2;
#pragma unroll
        for (int mt = 0; mt < 2; mt++) {
            int r0 = mrow + mt * 16 + rb;
#pragma unroll
            for (int j = 0; j < 2; j++) {
                int cc = j * 8 + c2;
                *(float2*)&P[(wn * 64 + r0) * PSTRIDE + cc] = make_float2(d[mt][j][0], d[mt][j][1]);
                *(float2*)&P[(wn * 64 + r0 + 8) * PSTRIDE + cc] = make_float2(d[mt][j][2], d[mt][j][3]);
            }
        }
    }
    __syncthreads();
    {
        const float* P = (const float*)smc;
        int row = t >> 2;
        int cq = (t & 3) * 4;
        float4 s0 = *(const float4*)&P[(0 * 64 + row) * PSTRIDE + cq];
        float4 s1 = *(const float4*)&P[(1 * 64 + row) * PSTRIDE + cq];
        float4 s2 = *(const float4*)&P[(2 * 64 + row) * PSTRIDE + cq];
        float4 s3 = *(const float4*)&P[(3 * 64 + row) * PSTRIDE + cq];
        float4 bv = *(const float4*)(b2 + cq);
        float4 o;
        o.x = s0.x + s1.x + s2.x + s3.x + bv.x;
        o.y = s0.y + s1.y + s2.y + s3.y + bv.y;
        o.z = s0.z + s1.z + s2.z + s3.z + bv.z;
        o.w = s0.w + s1.w + s2.w + s3.w + bv.w;
        *(float4*)(out + (size_t)(g0 + row) * KOUT + cq) = o;
    }
}

// =======================================================================
extern "C" void kernel_launch(void* const* d_in, const int* in_sizes, int n_in,
                              void* d_out, int out_size) {
    (void)in_sizes; (void)n_in; (void)out_size;
    const float* pt = (const float*)d_in[0];
    const float* vf = (const float*)d_in[1];
    const float* vc = (const float*)d_in[2];
    const float* Km = (const float*)d_in[3];
    const float* Rt = (const float*)d_in[4];
    const float* W1 = (const float*)d_in[5];
    const float* b1 = (const float*)d_in[6];
    const float* W2 = (const float*)d_in[7];
    const float* b2 = (const float*)d_in[8];
    float* out = (float*)d_out;

    const int total4 = KB * KM * KDIM / 4;
    mean_kernel<<<(total4 + 255) / 256, 256>>>(pt);

    const int prep_items = 256 * 64 + 16 * 256 + 256 * 384;
    prep_kernel<<<(prep_items + 255) / 256, 256>>>(W1, W2);

    cudaFuncSetAttribute(table_mma_kernel,
                         cudaFuncAttributeMaxDynamicSharedMemorySize,
                         TSMEM_BYTES);
    dim3 gridT(ROWS_PAD / 64, 2);
    table_mma_kernel<<<gridT, 256, TSMEM_BYTES>>>(b1);

    cudaFuncSetAttribute(fused_kernel,
                         cudaFuncAttributeMaxDynamicSharedMemorySize,
                         SMEMC_BYTES);
    fused_kernel<<<KGV / VB, 256, SMEMC_BYTES>>>(vf, vc, Km, Rt, b2, out);
}